// round 12
// baseline (speedup 1.0000x reference)
#include <cuda_runtime.h>
#include <math.h>

#define Bb 8
#define Nn 2048
#define Kk 20

// ---------------- scratch (static device globals; no allocation) -------------
__device__ float g_pd[(size_t)Bb * Nn * Nn];     // 134 MB distance matrix
__device__ int   g_idx[Bb * Nn * Kk];            // knn indices
__device__ float g_sq[Bb * Nn];                  // squared norms
__device__ float g_h[(size_t)Bb * 256 * Nn];     // concat buffer (max 256 ch)
__device__ float g_att[(size_t)Bb * 128 * Nn];   // attention weighted-diff M
__device__ float g_qk[(size_t)Bb * 128 * Nn];    // Wqk @ X
__device__ float g_xt[(size_t)Bb * Nn * 128];    // X transposed [B,N,C]
__device__ float g_qkt[(size_t)Bb * Nn * 128];   // QK transposed [B,N,C]
__device__ float g_wqk[128 * 128];               // wk^T wq
__device__ float g_wcv[128 * 128];               // wc wv
__device__ float g_xc[(size_t)Bb * 512 * Nn];    // x1|x2|x3|x4 concat
__device__ float g_x5[(size_t)Bb * 1024 * Nn];   // conv5 output
__device__ float g_mean[1024];
__device__ float g_rstd[1024];
__device__ float g_p[Bb * 2048];
__device__ float g_f1[Bb * 512];
__device__ float g_f2[Bb * 256];

// ---------------- kernels ----------------------------------------------------

__global__ void k_sqnorm(const float* __restrict__ X, long bsx, int C,
                         float* __restrict__ sq) {
    int i = blockIdx.x * blockDim.x + threadIdx.x;
    if (i >= Bb * Nn) return;
    int b = i / Nn, n = i % Nn;
    const float* xp = X + (long)b * bsx + n;
    float s = 0.f;
    for (int c = 0; c < C; c++) { float v = xp[(long)c * Nn]; s += v * v; }
    sq[i] = s;
}

// -------- high-throughput fp32 GEMM --------
// Y[b][o][n] = sum_c A[b?][o][c] * X[b][c][n]
// A row-major [O x C] (lda=C), optional batch stride bsa. BN=128, TN=8, KT=16.
// dist!=0: Y = sq[o] + sq[n] - 2*acc, diag=INF (A is XT, O==Nn).
template<int BM, int TM>
__global__ void k_gemm(const float* __restrict__ A, long bsa, int lda,
                       const float* __restrict__ X, long bsx,
                       int C, int O,
                       float* __restrict__ Y, long bsy,
                       const float* __restrict__ sq, int dist) {
    const int BN = 128, TN = 8, KT = 16;
    __shared__ float sA[KT][BM + 4];
    __shared__ float sX[KT][BN];
    int b  = blockIdx.z;
    int n0 = blockIdx.x * BN;
    int o0 = blockIdx.y * BM;
    int t  = threadIdx.x;          // 256 threads
    int tx = t & 15, ty = t >> 4;
    const float* Ab = A + (long)b * bsa;
    const float* Xb = X + (long)b * bsx;

    float acc[TM][TN];
    #pragma unroll
    for (int i = 0; i < TM; i++)
        #pragma unroll
        for (int j = 0; j < TN; j++) acc[i][j] = 0.f;

    for (int k0 = 0; k0 < C; k0 += KT) {
        #pragma unroll
        for (int u = 0; u < (BM * KT) / 256; u++) {
            int e = t + u * 256;
            int c = e & 15, o = e >> 4;
            float v = 0.f;
            if (k0 + c < C && o0 + o < O) v = Ab[(long)(o0 + o) * lda + k0 + c];
            sA[c][o] = v;
        }
        #pragma unroll
        for (int u = 0; u < (KT * BN) / 256; u++) {
            int e = t + u * 256;
            int n = e & 127, c = e >> 7;
            float v = 0.f;
            if (k0 + c < C) v = Xb[(long)(k0 + c) * Nn + n0 + n];
            sX[c][n] = v;
        }
        __syncthreads();
        #pragma unroll
        for (int kk = 0; kk < KT; kk++) {
            float a[TM], x[TN];
            #pragma unroll
            for (int i = 0; i < TM; i += 4)
                *(float4*)&a[i] = *(const float4*)&sA[kk][ty * TM + i];
            #pragma unroll
            for (int j = 0; j < TN; j += 4)
                *(float4*)&x[j] = *(const float4*)&sX[kk][tx * TN + j];
            #pragma unroll
            for (int i = 0; i < TM; i++)
                #pragma unroll
                for (int j = 0; j < TN; j++) acc[i][j] += a[i] * x[j];
        }
        __syncthreads();
    }

    if (!dist) {
        #pragma unroll
        for (int i = 0; i < TM; i++) {
            int o = o0 + ty * TM + i;
            if (o >= O) continue;
            float* yp = Y + (long)b * bsy + (long)o * Nn + n0 + tx * TN;
            *(float4*)yp       = *(float4*)&acc[i][0];
            *(float4*)(yp + 4) = *(float4*)&acc[i][4];
        }
    } else {
        #pragma unroll
        for (int i = 0; i < TM; i++) {
            int o = o0 + ty * TM + i;
            float sqo = sq[b * Nn + o];
            float4 r[2];
            #pragma unroll
            for (int j = 0; j < TN; j++) {
                int n = n0 + tx * TN + j;
                float d = sqo + sq[b * Nn + n] - 2.f * acc[i][j];
                if (n == o) d = 3.0e38f;
                ((float*)r)[j] = d;
            }
            float* yp = Y + (long)b * bsy + (long)o * Nn + n0 + tx * TN;
            *(float4*)yp       = r[0];
            *(float4*)(yp + 4) = r[1];
        }
    }
}

// top-K smallest per row: register-resident warp-segment argmin + merge.
// 256 threads = 8 warps; each warp owns a 256-elem segment, 8 keys/lane in regs.
// key = orderable(dist bits) << 11 | col  (min => smallest dist, lowest index)
__global__ void k_topk(const float* __restrict__ pd, int* __restrict__ out) {
    __shared__ unsigned long long cand[8 * Kk];   // 160 candidates
    int row = blockIdx.x;                         // b*N + n
    int t = threadIdx.x, w = t >> 5, lane = t & 31;
    const unsigned FULL = 0xffffffffu;
    const float* p = pd + (long)row * Nn;

    // load my 8 keys (coalesced: seg + lane + 32*j)
    unsigned long long v[8];
    int seg = w * 256;
    #pragma unroll
    for (int j = 0; j < 8; j++) {
        int col = seg + lane + 32 * j;
        unsigned bts = __float_as_uint(p[col]);
        bts = (bts & 0x80000000u) ? ~bts : (bts | 0x80000000u);   // order-preserving
        v[j] = ((unsigned long long)bts << 11) | (unsigned)col;
    }
    // local min tree
    unsigned long long mymin;
    {
        unsigned long long m0 = v[0] < v[1] ? v[0] : v[1];
        unsigned long long m1 = v[2] < v[3] ? v[2] : v[3];
        unsigned long long m2 = v[4] < v[5] ? v[4] : v[5];
        unsigned long long m3 = v[6] < v[7] ? v[6] : v[7];
        m0 = m0 < m1 ? m0 : m1;  m2 = m2 < m3 ? m2 : m3;
        mymin = m0 < m2 ? m0 : m2;
    }

    // 20 selections per warp over its segment
    for (int s = 0; s < Kk; s++) {
        unsigned long long r = mymin;
        #pragma unroll
        for (int off = 16; off; off >>= 1) {
            unsigned long long o = __shfl_xor_sync(FULL, r, off);
            r = o < r ? o : r;
        }
        if (lane == 0) cand[w * Kk + s] = r;
        if (mymin == r) {                          // unique owner (idx in key)
            #pragma unroll
            for (int j = 0; j < 8; j++) if (v[j] == r) v[j] = ~0ULL;
            unsigned long long m0 = v[0] < v[1] ? v[0] : v[1];
            unsigned long long m1 = v[2] < v[3] ? v[2] : v[3];
            unsigned long long m2 = v[4] < v[5] ? v[4] : v[5];
            unsigned long long m3 = v[6] < v[7] ? v[6] : v[7];
            m0 = m0 < m1 ? m0 : m1;  m2 = m2 < m3 ? m2 : m3;
            mymin = m0 < m2 ? m0 : m2;
        }
    }
    __syncthreads();

    // merge 160 candidates -> 20 (warp 0), 5 keys per lane
    if (w == 0) {
        unsigned long long c[5];
        #pragma unroll
        for (int j = 0; j < 5; j++) c[j] = cand[lane + 32 * j];
        unsigned long long mn;
        {
            unsigned long long m0 = c[0] < c[1] ? c[0] : c[1];
            unsigned long long m1 = c[2] < c[3] ? c[2] : c[3];
            m0 = m0 < m1 ? m0 : m1;
            mn = m0 < c[4] ? m0 : c[4];
        }
        for (int s = 0; s < Kk; s++) {
            unsigned long long r = mn;
            #pragma unroll
            for (int off = 16; off; off >>= 1) {
                unsigned long long o = __shfl_xor_sync(FULL, r, off);
                r = o < r ? o : r;
            }
            if (lane == 0) out[(long)row * Kk + s] = (int)(r & 2047ULL);
            if (mn == r) {
                #pragma unroll
                for (int j = 0; j < 5; j++) if (c[j] == r) c[j] = ~0ULL;
                unsigned long long m0 = c[0] < c[1] ? c[0] : c[1];
                unsigned long long m1 = c[2] < c[3] ? c[2] : c[3];
                m0 = m0 < m1 ? m0 : m1;
                mn = m0 < c[4] ? m0 : c[4];
            }
        }
    }
}

// transpose [B,C,N] -> [B,N,C]
__global__ void k_transpose(const float* __restrict__ X, long bsx, int C,
                            float* __restrict__ XT) {
    __shared__ float tile[32][33];
    int b = blockIdx.z;
    int n0 = blockIdx.x * 32, c0 = blockIdx.y * 32;
    for (int i = threadIdx.y; i < 32; i += 8) {
        int c = c0 + i;
        tile[i][threadIdx.x] = (c < C) ? X[(long)b * bsx + (long)c * Nn + n0 + threadIdx.x] : 0.f;
    }
    __syncthreads();
    for (int i = threadIdx.y; i < 32; i += 8) {
        int n = n0 + i, c = c0 + threadIdx.x;
        if (c < C) XT[((long)b * Nn + n) * C + c] = tile[threadIdx.x][i];
    }
}

// Wqk[i][j] = sum_e wk[e][i] * wq[e][j]
__global__ void k_wqk(const float* __restrict__ wk, const float* __restrict__ wq,
                      float* __restrict__ out, int C) {
    int j = blockIdx.x * 16 + threadIdx.x;
    int i = blockIdx.y * 16 + threadIdx.y;
    if (i >= C || j >= C) return;
    float a = 0.f;
    for (int e = 0; e < C; e++) a += wk[e * C + i] * wq[e * C + j];
    out[i * C + j] = a;
}

// Wcv[i][j] = sum_v wc[i][v] * wv[v][j]
__global__ void k_wcv(const float* __restrict__ wc, const float* __restrict__ wv,
                      float* __restrict__ out, int C) {
    int j = blockIdx.x * 16 + threadIdx.x;
    int i = blockIdx.y * 16 + threadIdx.y;
    if (i >= C || j >= C) return;
    float a = 0.f;
    for (int v = 0; v < C; v++) a += wc[i * C + v] * wv[v * C + j];
    out[i * C + j] = a;
}

// attention gather/softmax: one warp per point, 32 points per block
__global__ void k_attn2(const float* __restrict__ XT, const float* __restrict__ QKT,
                        int C, const int* __restrict__ idx,
                        float* __restrict__ M, long bsm) {
    __shared__ float s_m[128][33];
    const unsigned FULL = 0xffffffffu;
    int w = threadIdx.x >> 5, lane = threadIdx.x & 31;
    int pt = blockIdx.x * 32 + w;
    int b = pt / Nn;
    int n0 = (blockIdx.x & 63) * 32;
    int NR = (C + 31) >> 5;

    float qk[4], f[4];
    const float* qrow = QKT + (long)pt * C;
    const float* frow = XT + (long)pt * C;
    #pragma unroll
    for (int r = 0; r < 4; r++) {
        int c = lane + 32 * r;
        bool ok = (r < NR) && (c < C);
        qk[r] = ok ? qrow[c] : 0.f;
        f[r]  = ok ? frow[c] : 0.f;
    }
    const int* ip = idx + (long)pt * Kk;

    float myscore = 0.f;
    for (int j = 0; j < Kk; j++) {
        int ij = ip[j];
        const float* nrow = XT + ((long)b * Nn + ij) * C;
        float p = 0.f;
        #pragma unroll
        for (int r = 0; r < 4; r++) {
            int c = lane + 32 * r;
            if (r < NR && c < C) p += qk[r] * nrow[c];
        }
        #pragma unroll
        for (int off = 16; off > 0; off >>= 1) p += __shfl_xor_sync(FULL, p, off);
        if (lane == j) myscore = p;
    }
    float scale = rsqrtf((float)C);
    float val = (lane < Kk) ? myscore * scale : -3.0e38f;
    float mx = val;
    #pragma unroll
    for (int off = 16; off > 0; off >>= 1) mx = fmaxf(mx, __shfl_xor_sync(FULL, mx, off));
    float e = (lane < Kk) ? expf(val - mx) : 0.f;
    float sm = e;
    #pragma unroll
    for (int off = 16; off > 0; off >>= 1) sm += __shfl_xor_sync(FULL, sm, off);
    float wme = e / sm;

    float m[4] = {0.f, 0.f, 0.f, 0.f};
    for (int j = 0; j < Kk; j++) {
        float wj = __shfl_sync(FULL, wme, j);
        int ij = ip[j];
        const float* nrow = XT + ((long)b * Nn + ij) * C;
        #pragma unroll
        for (int r = 0; r < 4; r++) {
            int c = lane + 32 * r;
            if (r < NR && c < C) m[r] += wj * nrow[c];
        }
    }
    #pragma unroll
    for (int r = 0; r < 4; r++) m[r] -= f[r];

    #pragma unroll
    for (int r = 0; r < 4; r++) {
        int c = lane + 32 * r;
        if (r < NR && c < C) s_m[c][w] = m[r];
    }
    __syncthreads();
    int t = threadIdx.x;
    for (int e2 = t; e2 < C * 32; e2 += 1024) {
        int c = e2 >> 5, p2 = e2 & 31;
        M[(long)b * bsm + (long)c * Nn + n0 + p2] = s_m[c][p2];
    }
}

// per-channel batch stats over (B,N)
__global__ void k_bnstats(const float* __restrict__ Y, long bsy,
                          float* __restrict__ mean, float* __restrict__ rstd) {
    int o = blockIdx.x;
    int t = threadIdx.x;
    float s1 = 0.f, s2 = 0.f;
    for (int i = t; i < Bb * Nn; i += 256) {
        int b = i / Nn, n = i % Nn;
        float v = Y[(long)b * bsy + (long)o * Nn + n];
        s1 += v; s2 += v * v;
    }
    __shared__ float r1[256], r2[256];
    r1[t] = s1; r2[t] = s2;
    __syncthreads();
    for (int off = 128; off > 0; off >>= 1) {
        if (t < off) { r1[t] += r1[t + off]; r2[t] += r2[t + off]; }
        __syncthreads();
    }
    if (t == 0) {
        float m = r1[0] / (float)(Bb * Nn);
        float v = r2[0] / (float)(Bb * Nn) - m * m;
        mean[o] = m;
        rstd[o] = rsqrtf(v + 1e-5f);
    }
}

__global__ void k_bnapply(float* __restrict__ Y, long bsy, int O,
                          const float* __restrict__ mean, const float* __restrict__ rstd) {
    long total = (long)Bb * O * Nn;
    for (long i = (long)blockIdx.x * blockDim.x + threadIdx.x; i < total;
         i += (long)gridDim.x * blockDim.x) {
        int n = (int)(i % Nn);
        long bo = i / Nn;
        int o = (int)(bo % O);
        int b = (int)(bo / O);
        float* p = Y + (long)b * bsy + (long)o * Nn + n;
        float v = (*p - mean[o]) * rstd[o];
        *p = v >= 0.f ? v : 0.2f * v;
    }
}

__global__ void k_copy(const float* __restrict__ X, long bsx,
                       float* __restrict__ D, long bsd, int C) {
    long total = (long)Bb * C * Nn;
    for (long i = (long)blockIdx.x * blockDim.x + threadIdx.x; i < total;
         i += (long)gridDim.x * blockDim.x) {
        int n = (int)(i % Nn);
        long bc = i / Nn;
        int c = (int)(bc % C);
        int b = (int)(bc / C);
        D[(long)b * bsd + (long)c * Nn + n] = X[(long)b * bsx + (long)c * Nn + n];
    }
}

__global__ void k_pool(const float* __restrict__ X5, float* __restrict__ p) {
    int bc = blockIdx.x;
    int b = bc / 1024, c = bc % 1024;
    const float* xp = X5 + ((long)b * 1024 + c) * Nn;
    int t = threadIdx.x;
    float mx = -3e38f, sm = 0.f;
    for (int n = t; n < Nn; n += 256) { float v = xp[n]; mx = fmaxf(mx, v); sm += v; }
    __shared__ float smx[256], ssm[256];
    smx[t] = mx; ssm[t] = sm;
    __syncthreads();
    for (int off = 128; off > 0; off >>= 1) {
        if (t < off) { smx[t] = fmaxf(smx[t], smx[t + off]); ssm[t] += ssm[t + off]; }
        __syncthreads();
    }
    if (t == 0) {
        p[b * 2048 + c]        = smx[0];
        p[b * 2048 + 1024 + c] = ssm[0] / (float)Nn;
    }
}

__global__ void k_linear(const float* __restrict__ in, const float* __restrict__ W,
                         const float* __restrict__ bias, float* __restrict__ out,
                         int I, int O) {
    int w = (blockIdx.x * blockDim.x + threadIdx.x) >> 5;
    int lane = threadIdx.x & 31;
    if (w >= Bb * O) return;
    int b = w / O, o = w % O;
    const float* ip = in + (long)b * I;
    const float* wp = W + (long)o * I;
    float a = 0.f;
    for (int i = lane; i < I; i += 32) a += ip[i] * wp[i];
    for (int off = 16; off > 0; off >>= 1) a += __shfl_down_sync(0xffffffffu, a, off);
    if (lane == 0) out[w] = a + bias[o];
}

__global__ void k_bnf(float* __restrict__ Y, int O) {
    int o = blockIdx.x * blockDim.x + threadIdx.x;
    if (o >= O) return;
    float s1 = 0.f, s2 = 0.f;
    for (int b = 0; b < Bb; b++) { float v = Y[b * O + o]; s1 += v; s2 += v * v; }
    float m = s1 / (float)Bb;
    float v = s2 / (float)Bb - m * m;
    float r = rsqrtf(v + 1e-5f);
    for (int b = 0; b < Bb; b++) {
        float u = (Y[b * O + o] - m) * r;
        Y[b * O + o] = u >= 0.f ? u : 0.2f * u;
    }
}

// ---------------- host orchestration ----------------------------------------

static void gemm_h(const float* A, long bsa, int lda, const float* X, long bsx,
                   int C, int O, float* Y, long bsy, const float* sq, int dist) {
    if (O % 128 == 0) {
        dim3 g(Nn / 128, O / 128, Bb);
        k_gemm<128, 8><<<g, 256>>>(A, bsa, lda, X, bsx, C, O, Y, bsy, sq, dist);
    } else {
        dim3 g(Nn / 128, (O + 63) / 64, Bb);
        k_gemm<64, 4><<<g, 256>>>(A, bsa, lda, X, bsx, C, O, Y, bsy, sq, dist);
    }
}

struct Scratch {
    float *pd, *sq, *att, *qk, *xt, *qkt, *wqk, *wcv, *h, *xc, *x5, *mean, *rstd, *p, *f1, *f2;
    int* idx;
};

static void conv_bn_h(const float* X, long bsx, int C, const float* W, int O,
                      float* Y, long bsy, float* mean, float* rstd) {
    gemm_h(W, 0, C, X, bsx, C, O, Y, bsy, nullptr, 0);
    k_bnstats<<<O, 256>>>(Y, bsy, mean, rstd);
    long total = (long)Bb * O * Nn;
    k_bnapply<<<(int)((total + 255) / 256), 256>>>(Y, bsy, O, mean, rstd);
}

static void self_att_h(const float* X, long bsx, int C,
                       const float* wq, const float* wk, const float* wv, const float* wc,
                       float* H, long bsh, const Scratch& S) {
    k_sqnorm<<<(Bb * Nn + 255) / 256, 256>>>(X, bsx, C, S.sq);

    // transpose X -> XT [B,N,C]
    dim3 tg(Nn / 32, (C + 31) / 32, Bb);
    k_transpose<<<tg, dim3(32, 8)>>>(X, bsx, C, S.xt);

    // dist = GEMM(A=XT, X) with dist epilogue
    gemm_h(S.xt, (long)Nn * C, C, X, bsx, C, Nn, S.pd, (long)Nn * Nn, S.sq, 1);
    k_topk<<<Bb * Nn, 256>>>(S.pd, S.idx);

    // Wqk = wk^T wq ; QK = Wqk @ X ; transpose -> QKT
    dim3 sg((C + 15) / 16, (C + 15) / 16);
    k_wqk<<<sg, dim3(16, 16)>>>(wk, wq, S.wqk, C);
    gemm_h(S.wqk, 0, C, X, bsx, C, C, S.qk, (long)C * Nn, nullptr, 0);
    k_transpose<<<tg, dim3(32, 8)>>>(S.qk, (long)C * Nn, C, S.qkt);

    // gather + softmax + weighted diff -> M
    k_attn2<<<Bb * Nn / 32, 1024>>>(S.xt, S.qkt, C, S.idx, S.att, (long)C * Nn);

    // res = conv_bn(Wcv @ M)
    k_wcv<<<sg, dim3(16, 16)>>>(wc, wv, S.wcv, C);
    conv_bn_h(S.att, (long)C * Nn, C, S.wcv, C, H, bsh, S.mean, S.rstd);

    // concat raw x into channels [C, 2C)
    long total = (long)Bb * C * Nn;
    k_copy<<<(int)((total + 255) / 256), 256>>>(X, bsx, H + (long)C * Nn, bsh, C);
}

extern "C" void kernel_launch(void* const* d_in, const int* in_sizes, int n_in,
                              void* d_out, int out_size) {
    const float* x = (const float*)d_in[0];
    const float* sa_wq[4] = {(const float*)d_in[1],  (const float*)d_in[5],
                             (const float*)d_in[9],  (const float*)d_in[13]};
    const float* sa_wk[4] = {(const float*)d_in[2],  (const float*)d_in[6],
                             (const float*)d_in[10], (const float*)d_in[14]};
    const float* sa_wv[4] = {(const float*)d_in[3],  (const float*)d_in[7],
                             (const float*)d_in[11], (const float*)d_in[15]};
    const float* sa_wc[4] = {(const float*)d_in[4],  (const float*)d_in[8],
                             (const float*)d_in[12], (const float*)d_in[16]};
    const float* conv1_w = (const float*)d_in[17];
    const float* conv2_w = (const float*)d_in[18];
    const float* conv3_w = (const float*)d_in[19];
    const float* conv4_w = (const float*)d_in[20];
    const float* conv5_w = (const float*)d_in[21];
    const float* lin1_w = (const float*)d_in[22];
    const float* lin1_b = (const float*)d_in[23];
    const float* lin2_w = (const float*)d_in[24];
    const float* lin2_b = (const float*)d_in[25];
    const float* lin3_w = (const float*)d_in[26];
    const float* lin3_b = (const float*)d_in[27];

    Scratch S;
    cudaGetSymbolAddress((void**)&S.pd,   g_pd);
    cudaGetSymbolAddress((void**)&S.idx,  g_idx);
    cudaGetSymbolAddress((void**)&S.sq,   g_sq);
    cudaGetSymbolAddress((void**)&S.h,    g_h);
    cudaGetSymbolAddress((void**)&S.att,  g_att);
    cudaGetSymbolAddress((void**)&S.qk,   g_qk);
    cudaGetSymbolAddress((void**)&S.xt,   g_xt);
    cudaGetSymbolAddress((void**)&S.qkt,  g_qkt);
    cudaGetSymbolAddress((void**)&S.wqk,  g_wqk);
    cudaGetSymbolAddress((void**)&S.wcv,  g_wcv);
    cudaGetSymbolAddress((void**)&S.xc,   g_xc);
    cudaGetSymbolAddress((void**)&S.x5,   g_x5);
    cudaGetSymbolAddress((void**)&S.mean, g_mean);
    cudaGetSymbolAddress((void**)&S.rstd, g_rstd);
    cudaGetSymbolAddress((void**)&S.p,    g_p);
    cudaGetSymbolAddress((void**)&S.f1,   g_f1);
    cudaGetSymbolAddress((void**)&S.f2,   g_f2);

    const long bxc = (long)512 * Nn;

    self_att_h(x, (long)3 * Nn, 3, sa_wq[0], sa_wk[0], sa_wv[0], sa_wc[0],
               S.h, (long)6 * Nn, S);
    conv_bn_h(S.h, (long)6 * Nn, 6, conv1_w, 64, S.xc, bxc, S.mean, S.rstd);

    self_att_h(S.xc, bxc, 64, sa_wq[1], sa_wk[1], sa_wv[1], sa_wc[1],
               S.h, (long)128 * Nn, S);
    conv_bn_h(S.h, (long)128 * Nn, 128, conv2_w, 64, S.xc + (long)64 * Nn, bxc, S.mean, S.rstd);

    self_att_h(S.xc + (long)64 * Nn, bxc, 64, sa_wq[2], sa_wk[2], sa_wv[2], sa_wc[2],
               S.h, (long)128 * Nn, S);
    conv_bn_h(S.h, (long)128 * Nn, 128, conv3_w, 128, S.xc + (long)128 * Nn, bxc, S.mean, S.rstd);

    self_att_h(S.xc + (long)128 * Nn, bxc, 128, sa_wq[3], sa_wk[3], sa_wv[3], sa_wc[3],
               S.h, (long)256 * Nn, S);
    conv_bn_h(S.h, (long)256 * Nn, 256, conv4_w, 256, S.xc + (long)256 * Nn, bxc, S.mean, S.rstd);

    conv_bn_h(S.xc, bxc, 512, conv5_w, 1024, S.x5, (long)1024 * Nn, S.mean, S.rstd);

    k_pool<<<Bb * 1024, 256>>>(S.x5, S.p);

    k_linear<<<(Bb * 512 + 7) / 8, 256>>>(S.p, lin1_w, lin1_b, S.f1, 2048, 512);
    k_bnf<<<2, 256>>>(S.f1, 512);
    k_linear<<<(Bb * 256 + 7) / 8, 256>>>(S.f1, lin2_w, lin2_b, S.f2, 512, 256);
    k_bnf<<<1, 256>>>(S.f2, 256);
    k_linear<<<(Bb * 40 + 7) / 8, 256>>>(S.f2, lin3_w, lin3_b, (float*)d_out, 256, 40);
}

// round 13
// speedup vs baseline: 1.2172x; 1.2172x over previous
#include <cuda_runtime.h>
#include <math.h>

#define Bb 8
#define Nn 2048
#define Kk 20

// ---------------- scratch (static device globals; no allocation) -------------
__device__ float g_pd[(size_t)Bb * Nn * Nn];     // 134 MB distance matrix
__device__ int   g_idx[Bb * Nn * Kk];            // knn indices
__device__ float g_sq[Bb * Nn];                  // squared norms
__device__ float g_h[(size_t)Bb * 256 * Nn];     // concat buffer (max 256 ch)
__device__ float g_att[(size_t)Bb * 128 * Nn];   // attention weighted-diff M
__device__ float g_qk[(size_t)Bb * 128 * Nn];    // Wqk @ X
__device__ float g_xt[(size_t)Bb * Nn * 128];    // X transposed [B,N,C]
__device__ float g_qkt[(size_t)Bb * Nn * 128];   // QK transposed [B,N,C]
__device__ float g_wqk[128 * 128];               // wk^T wq
__device__ float g_wcv[128 * 128];               // wc wv
__device__ float g_xc[(size_t)Bb * 512 * Nn];    // x1|x2|x3|x4 concat
__device__ float g_x5[(size_t)Bb * 1024 * Nn];   // conv5 output
__device__ float g_mean[1024];
__device__ float g_rstd[1024];
__device__ float g_p[Bb * 2048];
__device__ float g_f1[Bb * 512];
__device__ float g_f2[Bb * 256];

// ---------------- kernels ----------------------------------------------------

__global__ void k_sqnorm(const float* __restrict__ X, long bsx, int C,
                         float* __restrict__ sq) {
    int i = blockIdx.x * blockDim.x + threadIdx.x;
    if (i >= Bb * Nn) return;
    int b = i / Nn, n = i % Nn;
    const float* xp = X + (long)b * bsx + n;
    float s = 0.f;
    for (int c = 0; c < C; c++) { float v = xp[(long)c * Nn]; s += v * v; }
    sq[i] = s;
}

// -------- high-throughput fp32 GEMM --------
// Y[b][o][n] = sum_c A[b?][o][c] * X[b][c][n]
// dist!=0: Y = sq[o] + sq[n] - 2*acc, diag=INF (A is XT, O==Nn).
template<int BM, int TM>
__global__ void k_gemm(const float* __restrict__ A, long bsa, int lda,
                       const float* __restrict__ X, long bsx,
                       int C, int O,
                       float* __restrict__ Y, long bsy,
                       const float* __restrict__ sq, int dist) {
    const int BN = 128, TN = 8, KT = 16;
    __shared__ float sA[KT][BM + 4];
    __shared__ float sX[KT][BN];
    int b  = blockIdx.z;
    int n0 = blockIdx.x * BN;
    int o0 = blockIdx.y * BM;
    int t  = threadIdx.x;          // 256 threads
    int tx = t & 15, ty = t >> 4;
    const float* Ab = A + (long)b * bsa;
    const float* Xb = X + (long)b * bsx;

    float acc[TM][TN];
    #pragma unroll
    for (int i = 0; i < TM; i++)
        #pragma unroll
        for (int j = 0; j < TN; j++) acc[i][j] = 0.f;

    for (int k0 = 0; k0 < C; k0 += KT) {
        #pragma unroll
        for (int u = 0; u < (BM * KT) / 256; u++) {
            int e = t + u * 256;
            int c = e & 15, o = e >> 4;
            float v = 0.f;
            if (k0 + c < C && o0 + o < O) v = Ab[(long)(o0 + o) * lda + k0 + c];
            sA[c][o] = v;
        }
        #pragma unroll
        for (int u = 0; u < (KT * BN) / 256; u++) {
            int e = t + u * 256;
            int n = e & 127, c = e >> 7;
            float v = 0.f;
            if (k0 + c < C) v = Xb[(long)(k0 + c) * Nn + n0 + n];
            sX[c][n] = v;
        }
        __syncthreads();
        #pragma unroll
        for (int kk = 0; kk < KT; kk++) {
            float a[TM], x[TN];
            #pragma unroll
            for (int i = 0; i < TM; i += 4)
                *(float4*)&a[i] = *(const float4*)&sA[kk][ty * TM + i];
            #pragma unroll
            for (int j = 0; j < TN; j += 4)
                *(float4*)&x[j] = *(const float4*)&sX[kk][tx * TN + j];
            #pragma unroll
            for (int i = 0; i < TM; i++)
                #pragma unroll
                for (int j = 0; j < TN; j++) acc[i][j] += a[i] * x[j];
        }
        __syncthreads();
    }

    if (!dist) {
        #pragma unroll
        for (int i = 0; i < TM; i++) {
            int o = o0 + ty * TM + i;
            if (o >= O) continue;
            float* yp = Y + (long)b * bsy + (long)o * Nn + n0 + tx * TN;
            *(float4*)yp       = *(float4*)&acc[i][0];
            *(float4*)(yp + 4) = *(float4*)&acc[i][4];
        }
    } else {
        #pragma unroll
        for (int i = 0; i < TM; i++) {
            int o = o0 + ty * TM + i;
            float sqo = sq[b * Nn + o];
            float4 r[2];
            #pragma unroll
            for (int j = 0; j < TN; j++) {
                int n = n0 + tx * TN + j;
                float d = sqo + sq[b * Nn + n] - 2.f * acc[i][j];
                if (n == o) d = 3.0e38f;
                ((float*)r)[j] = d;
            }
            float* yp = Y + (long)b * bsy + (long)o * Nn + n0 + tx * TN;
            *(float4*)yp       = r[0];
            *(float4*)(yp + 4) = r[1];
        }
    }
}

// top-K smallest per row via 12-bit histogram select + small iterative argmin.
// key = order-preserving u32 of float; bin = key >> 20 (4096 bins).
// Find minimal bin B with cum >= K; candidates = keys with bin <= B (typ. ~100).
// Exact: final selection uses u64 (keybits << 11 | col) => lowest-index ties.
__global__ void k_topk(const float* __restrict__ pd, int* __restrict__ out) {
    __shared__ unsigned int hist[4096];
    __shared__ unsigned long long cand[2080];
    __shared__ unsigned int warpsum[8];
    __shared__ unsigned int s_B;
    __shared__ unsigned int s_nc;
    int row = blockIdx.x;                         // b*N + n
    int t = threadIdx.x, w = t >> 5, lane = t & 31;
    const unsigned FULL = 0xffffffffu;
    const float* p = pd + (long)row * Nn;

    #pragma unroll
    for (int i = 0; i < 16; i++) hist[t + 256 * i] = 0;
    if (t == 0) s_nc = 0;
    __syncthreads();

    // load 8 keys/thread (coalesced) + histogram
    unsigned key[8];
    #pragma unroll
    for (int j = 0; j < 8; j++) {
        unsigned bts = __float_as_uint(p[t + 256 * j]);
        bts = (bts & 0x80000000u) ? ~bts : (bts | 0x80000000u);   // order-preserving
        key[j] = bts;
        atomicAdd(&hist[bts >> 20], 1u);
    }
    __syncthreads();

    // block scan over per-thread partials (16 consecutive bins each)
    unsigned partial = 0;
    #pragma unroll
    for (int i = 0; i < 16; i++) partial += hist[t * 16 + i];
    unsigned incl = partial;
    #pragma unroll
    for (int off = 1; off < 32; off <<= 1) {
        unsigned v = __shfl_up_sync(FULL, incl, off);
        if (lane >= off) incl += v;
    }
    if (lane == 31) warpsum[w] = incl;
    __syncthreads();
    if (w == 0) {
        unsigned v = (lane < 8) ? warpsum[lane] : 0;
        #pragma unroll
        for (int off = 1; off < 8; off <<= 1) {
            unsigned u = __shfl_up_sync(FULL, v, off);
            if (lane >= off) v += u;
        }
        if (lane < 8) warpsum[lane] = v;
    }
    __syncthreads();
    if (w > 0) incl += warpsum[w - 1];
    unsigned excl = incl - partial;
    if (excl < Kk && Kk <= incl) {                // unique thread owns bin B
        unsigned cum = excl;
        for (int i = 0; i < 16; i++) {
            cum += hist[t * 16 + i];
            if (cum >= Kk) { s_B = t * 16 + i; break; }
        }
    }
    __syncthreads();
    unsigned B = s_B;

    // compact candidates (bin <= B); count(<B) <= 19 so >= 20 total, <= 2048
    #pragma unroll
    for (int j = 0; j < 8; j++) {
        if ((key[j] >> 20) <= B) {
            unsigned pos = atomicAdd(&s_nc, 1u);
            cand[pos] = ((unsigned long long)key[j] << 11) | (unsigned)(t + 256 * j);
        }
    }
    __syncthreads();
    int nc = (int)s_nc;

    // warp 0: 20 iterative argmin selections over the small candidate set
    if (w == 0) {
        for (int s = 0; s < Kk; s++) {
            unsigned long long mn = ~0ULL; int mi = -1;
            for (int i = lane; i < nc; i += 32) {
                unsigned long long v = cand[i];
                if (v < mn) { mn = v; mi = i; }
            }
            unsigned long long r = mn;
            #pragma unroll
            for (int off = 16; off; off >>= 1) {
                unsigned long long o = __shfl_xor_sync(FULL, r, off);
                r = o < r ? o : r;
            }
            if (lane == 0) out[(long)row * Kk + s] = (int)(r & 2047ULL);
            if (mn == r) cand[mi] = ~0ULL;        // unique owner clears
        }
    }
}

// transpose [B,C,N] -> [B,N,C]
__global__ void k_transpose(const float* __restrict__ X, long bsx, int C,
                            float* __restrict__ XT) {
    __shared__ float tile[32][33];
    int b = blockIdx.z;
    int n0 = blockIdx.x * 32, c0 = blockIdx.y * 32;
    for (int i = threadIdx.y; i < 32; i += 8) {
        int c = c0 + i;
        tile[i][threadIdx.x] = (c < C) ? X[(long)b * bsx + (long)c * Nn + n0 + threadIdx.x] : 0.f;
    }
    __syncthreads();
    for (int i = threadIdx.y; i < 32; i += 8) {
        int n = n0 + i, c = c0 + threadIdx.x;
        if (c < C) XT[((long)b * Nn + n) * C + c] = tile[threadIdx.x][i];
    }
}

// Wqk[i][j] = sum_e wk[e][i] * wq[e][j]
__global__ void k_wqk(const float* __restrict__ wk, const float* __restrict__ wq,
                      float* __restrict__ out, int C) {
    int j = blockIdx.x * 16 + threadIdx.x;
    int i = blockIdx.y * 16 + threadIdx.y;
    if (i >= C || j >= C) return;
    float a = 0.f;
    for (int e = 0; e < C; e++) a += wk[e * C + i] * wq[e * C + j];
    out[i * C + j] = a;
}

// Wcv[i][j] = sum_v wc[i][v] * wv[v][j]
__global__ void k_wcv(const float* __restrict__ wc, const float* __restrict__ wv,
                      float* __restrict__ out, int C) {
    int j = blockIdx.x * 16 + threadIdx.x;
    int i = blockIdx.y * 16 + threadIdx.y;
    if (i >= C || j >= C) return;
    float a = 0.f;
    for (int v = 0; v < C; v++) a += wc[i * C + v] * wv[v * C + j];
    out[i * C + j] = a;
}

// attention gather/softmax: one warp per point, 32 points per block
__global__ void k_attn2(const float* __restrict__ XT, const float* __restrict__ QKT,
                        int C, const int* __restrict__ idx,
                        float* __restrict__ M, long bsm) {
    __shared__ float s_m[128][33];
    const unsigned FULL = 0xffffffffu;
    int w = threadIdx.x >> 5, lane = threadIdx.x & 31;
    int pt = blockIdx.x * 32 + w;
    int b = pt / Nn;
    int n0 = (blockIdx.x & 63) * 32;
    int NR = (C + 31) >> 5;

    float qk[4], f[4];
    const float* qrow = QKT + (long)pt * C;
    const float* frow = XT + (long)pt * C;
    #pragma unroll
    for (int r = 0; r < 4; r++) {
        int c = lane + 32 * r;
        bool ok = (r < NR) && (c < C);
        qk[r] = ok ? qrow[c] : 0.f;
        f[r]  = ok ? frow[c] : 0.f;
    }
    const int* ip = idx + (long)pt * Kk;

    float myscore = 0.f;
    for (int j = 0; j < Kk; j++) {
        int ij = ip[j];
        const float* nrow = XT + ((long)b * Nn + ij) * C;
        float p = 0.f;
        #pragma unroll
        for (int r = 0; r < 4; r++) {
            int c = lane + 32 * r;
            if (r < NR && c < C) p += qk[r] * nrow[c];
        }
        #pragma unroll
        for (int off = 16; off > 0; off >>= 1) p += __shfl_xor_sync(FULL, p, off);
        if (lane == j) myscore = p;
    }
    float scale = rsqrtf((float)C);
    float val = (lane < Kk) ? myscore * scale : -3.0e38f;
    float mx = val;
    #pragma unroll
    for (int off = 16; off > 0; off >>= 1) mx = fmaxf(mx, __shfl_xor_sync(FULL, mx, off));
    float e = (lane < Kk) ? expf(val - mx) : 0.f;
    float sm = e;
    #pragma unroll
    for (int off = 16; off > 0; off >>= 1) sm += __shfl_xor_sync(FULL, sm, off);
    float wme = e / sm;

    float m[4] = {0.f, 0.f, 0.f, 0.f};
    for (int j = 0; j < Kk; j++) {
        float wj = __shfl_sync(FULL, wme, j);
        int ij = ip[j];
        const float* nrow = XT + ((long)b * Nn + ij) * C;
        #pragma unroll
        for (int r = 0; r < 4; r++) {
            int c = lane + 32 * r;
            if (r < NR && c < C) m[r] += wj * nrow[c];
        }
    }
    #pragma unroll
    for (int r = 0; r < 4; r++) m[r] -= f[r];

    #pragma unroll
    for (int r = 0; r < 4; r++) {
        int c = lane + 32 * r;
        if (r < NR && c < C) s_m[c][w] = m[r];
    }
    __syncthreads();
    int t = threadIdx.x;
    for (int e2 = t; e2 < C * 32; e2 += 1024) {
        int c = e2 >> 5, p2 = e2 & 31;
        M[(long)b * bsm + (long)c * Nn + n0 + p2] = s_m[c][p2];
    }
}

// per-channel batch stats over (B,N)
__global__ void k_bnstats(const float* __restrict__ Y, long bsy,
                          float* __restrict__ mean, float* __restrict__ rstd) {
    int o = blockIdx.x;
    int t = threadIdx.x;
    float s1 = 0.f, s2 = 0.f;
    for (int i = t; i < Bb * Nn; i += 256) {
        int b = i / Nn, n = i % Nn;
        float v = Y[(long)b * bsy + (long)o * Nn + n];
        s1 += v; s2 += v * v;
    }
    __shared__ float r1[256], r2[256];
    r1[t] = s1; r2[t] = s2;
    __syncthreads();
    for (int off = 128; off > 0; off >>= 1) {
        if (t < off) { r1[t] += r1[t + off]; r2[t] += r2[t + off]; }
        __syncthreads();
    }
    if (t == 0) {
        float m = r1[0] / (float)(Bb * Nn);
        float v = r2[0] / (float)(Bb * Nn) - m * m;
        mean[o] = m;
        rstd[o] = rsqrtf(v + 1e-5f);
    }
}

__global__ void k_bnapply(float* __restrict__ Y, long bsy, int O,
                          const float* __restrict__ mean, const float* __restrict__ rstd) {
    long total = (long)Bb * O * Nn;
    for (long i = (long)blockIdx.x * blockDim.x + threadIdx.x; i < total;
         i += (long)gridDim.x * blockDim.x) {
        int n = (int)(i % Nn);
        long bo = i / Nn;
        int o = (int)(bo % O);
        int b = (int)(bo / O);
        float* p = Y + (long)b * bsy + (long)o * Nn + n;
        float v = (*p - mean[o]) * rstd[o];
        *p = v >= 0.f ? v : 0.2f * v;
    }
}

__global__ void k_copy(const float* __restrict__ X, long bsx,
                       float* __restrict__ D, long bsd, int C) {
    long total = (long)Bb * C * Nn;
    for (long i = (long)blockIdx.x * blockDim.x + threadIdx.x; i < total;
         i += (long)gridDim.x * blockDim.x) {
        int n = (int)(i % Nn);
        long bc = i / Nn;
        int c = (int)(bc % C);
        int b = (int)(bc / C);
        D[(long)b * bsd + (long)c * Nn + n] = X[(long)b * bsx + (long)c * Nn + n];
    }
}

__global__ void k_pool(const float* __restrict__ X5, float* __restrict__ p) {
    int bc = blockIdx.x;
    int b = bc / 1024, c = bc % 1024;
    const float* xp = X5 + ((long)b * 1024 + c) * Nn;
    int t = threadIdx.x;
    float mx = -3e38f, sm = 0.f;
    for (int n = t; n < Nn; n += 256) { float v = xp[n]; mx = fmaxf(mx, v); sm += v; }
    __shared__ float smx[256], ssm[256];
    smx[t] = mx; ssm[t] = sm;
    __syncthreads();
    for (int off = 128; off > 0; off >>= 1) {
        if (t < off) { smx[t] = fmaxf(smx[t], smx[t + off]); ssm[t] += ssm[t + off]; }
        __syncthreads();
    }
    if (t == 0) {
        p[b * 2048 + c]        = smx[0];
        p[b * 2048 + 1024 + c] = ssm[0] / (float)Nn;
    }
}

__global__ void k_linear(const float* __restrict__ in, const float* __restrict__ W,
                         const float* __restrict__ bias, float* __restrict__ out,
                         int I, int O) {
    int w = (blockIdx.x * blockDim.x + threadIdx.x) >> 5;
    int lane = threadIdx.x & 31;
    if (w >= Bb * O) return;
    int b = w / O, o = w % O;
    const float* ip = in + (long)b * I;
    const float* wp = W + (long)o * I;
    float a = 0.f;
    for (int i = lane; i < I; i += 32) a += ip[i] * wp[i];
    for (int off = 16; off > 0; off >>= 1) a += __shfl_down_sync(0xffffffffu, a, off);
    if (lane == 0) out[w] = a + bias[o];
}

__global__ void k_bnf(float* __restrict__ Y, int O) {
    int o = blockIdx.x * blockDim.x + threadIdx.x;
    if (o >= O) return;
    float s1 = 0.f, s2 = 0.f;
    for (int b = 0; b < Bb; b++) { float v = Y[b * O + o]; s1 += v; s2 += v * v; }
    float m = s1 / (float)Bb;
    float v = s2 / (float)Bb - m * m;
    float r = rsqrtf(v + 1e-5f);
    for (int b = 0; b < Bb; b++) {
        float u = (Y[b * O + o] - m) * r;
        Y[b * O + o] = u >= 0.f ? u : 0.2f * u;
    }
}

// ---------------- host orchestration ----------------------------------------

static void gemm_h(const float* A, long bsa, int lda, const float* X, long bsx,
                   int C, int O, float* Y, long bsy, const float* sq, int dist) {
    if (O % 128 == 0) {
        dim3 g(Nn / 128, O / 128, Bb);
        k_gemm<128, 8><<<g, 256>>>(A, bsa, lda, X, bsx, C, O, Y, bsy, sq, dist);
    } else {
        dim3 g(Nn / 128, (O + 63) / 64, Bb);
        k_gemm<64, 4><<<g, 256>>>(A, bsa, lda, X, bsx, C, O, Y, bsy, sq, dist);
    }
}

struct Scratch {
    float *pd, *sq, *att, *qk, *xt, *qkt, *wqk, *wcv, *h, *xc, *x5, *mean, *rstd, *p, *f1, *f2;
    int* idx;
};

static void conv_bn_h(const float* X, long bsx, int C, const float* W, int O,
                      float* Y, long bsy, float* mean, float* rstd) {
    gemm_h(W, 0, C, X, bsx, C, O, Y, bsy, nullptr, 0);
    k_bnstats<<<O, 256>>>(Y, bsy, mean, rstd);
    long total = (long)Bb * O * Nn;
    k_bnapply<<<(int)((total + 255) / 256), 256>>>(Y, bsy, O, mean, rstd);
}

static void self_att_h(const float* X, long bsx, int C,
                       const float* wq, const float* wk, const float* wv, const float* wc,
                       float* H, long bsh, const Scratch& S) {
    k_sqnorm<<<(Bb * Nn + 255) / 256, 256>>>(X, bsx, C, S.sq);

    // transpose X -> XT [B,N,C]
    dim3 tg(Nn / 32, (C + 31) / 32, Bb);
    k_transpose<<<tg, dim3(32, 8)>>>(X, bsx, C, S.xt);

    // dist = GEMM(A=XT, X) with dist epilogue
    gemm_h(S.xt, (long)Nn * C, C, X, bsx, C, Nn, S.pd, (long)Nn * Nn, S.sq, 1);
    k_topk<<<Bb * Nn, 256>>>(S.pd, S.idx);

    // Wqk = wk^T wq ; QK = Wqk @ X ; transpose -> QKT
    dim3 sg((C + 15) / 16, (C + 15) / 16);
    k_wqk<<<sg, dim3(16, 16)>>>(wk, wq, S.wqk, C);
    gemm_h(S.wqk, 0, C, X, bsx, C, C, S.qk, (long)C * Nn, nullptr, 0);
    k_transpose<<<tg, dim3(32, 8)>>>(S.qk, (long)C * Nn, C, S.qkt);

    // gather + softmax + weighted diff -> M
    k_attn2<<<Bb * Nn / 32, 1024>>>(S.xt, S.qkt, C, S.idx, S.att, (long)C * Nn);

    // res = conv_bn(Wcv @ M)
    k_wcv<<<sg, dim3(16, 16)>>>(wc, wv, S.wcv, C);
    conv_bn_h(S.att, (long)C * Nn, C, S.wcv, C, H, bsh, S.mean, S.rstd);

    // concat raw x into channels [C, 2C)
    long total = (long)Bb * C * Nn;
    k_copy<<<(int)((total + 255) / 256), 256>>>(X, bsx, H + (long)C * Nn, bsh, C);
}

extern "C" void kernel_launch(void* const* d_in, const int* in_sizes, int n_in,
                              void* d_out, int out_size) {
    const float* x = (const float*)d_in[0];
    const float* sa_wq[4] = {(const float*)d_in[1],  (const float*)d_in[5],
                             (const float*)d_in[9],  (const float*)d_in[13]};
    const float* sa_wk[4] = {(const float*)d_in[2],  (const float*)d_in[6],
                             (const float*)d_in[10], (const float*)d_in[14]};
    const float* sa_wv[4] = {(const float*)d_in[3],  (const float*)d_in[7],
                             (const float*)d_in[11], (const float*)d_in[15]};
    const float* sa_wc[4] = {(const float*)d_in[4],  (const float*)d_in[8],
                             (const float*)d_in[12], (const float*)d_in[16]};
    const float* conv1_w = (const float*)d_in[17];
    const float* conv2_w = (const float*)d_in[18];
    const float* conv3_w = (const float*)d_in[19];
    const float* conv4_w = (const float*)d_in[20];
    const float* conv5_w = (const float*)d_in[21];
    const float* lin1_w = (const float*)d_in[22];
    const float* lin1_b = (const float*)d_in[23];
    const float* lin2_w = (const float*)d_in[24];
    const float* lin2_b = (const float*)d_in[25];
    const float* lin3_w = (const float*)d_in[26];
    const float* lin3_b = (const float*)d_in[27];

    Scratch S;
    cudaGetSymbolAddress((void**)&S.pd,   g_pd);
    cudaGetSymbolAddress((void**)&S.idx,  g_idx);
    cudaGetSymbolAddress((void**)&S.sq,   g_sq);
    cudaGetSymbolAddress((void**)&S.h,    g_h);
    cudaGetSymbolAddress((void**)&S.att,  g_att);
    cudaGetSymbolAddress((void**)&S.qk,   g_qk);
    cudaGetSymbolAddress((void**)&S.xt,   g_xt);
    cudaGetSymbolAddress((void**)&S.qkt,  g_qkt);
    cudaGetSymbolAddress((void**)&S.wqk,  g_wqk);
    cudaGetSymbolAddress((void**)&S.wcv,  g_wcv);
    cudaGetSymbolAddress((void**)&S.xc,   g_xc);
    cudaGetSymbolAddress((void**)&S.x5,   g_x5);
    cudaGetSymbolAddress((void**)&S.mean, g_mean);
    cudaGetSymbolAddress((void**)&S.rstd, g_rstd);
    cudaGetSymbolAddress((void**)&S.p,    g_p);
    cudaGetSymbolAddress((void**)&S.f1,   g_f1);
    cudaGetSymbolAddress((void**)&S.f2,   g_f2);

    const long bxc = (long)512 * Nn;

    self_att_h(x, (long)3 * Nn, 3, sa_wq[0], sa_wk[0], sa_wv[0], sa_wc[0],
               S.h, (long)6 * Nn, S);
    conv_bn_h(S.h, (long)6 * Nn, 6, conv1_w, 64, S.xc, bxc, S.mean, S.rstd);

    self_att_h(S.xc, bxc, 64, sa_wq[1], sa_wk[1], sa_wv[1], sa_wc[1],
               S.h, (long)128 * Nn, S);
    conv_bn_h(S.h, (long)128 * Nn, 128, conv2_w, 64, S.xc + (long)64 * Nn, bxc, S.mean, S.rstd);

    self_att_h(S.xc + (long)64 * Nn, bxc, 64, sa_wq[2], sa_wk[2], sa_wv[2], sa_wc[2],
               S.h, (long)128 * Nn, S);
    conv_bn_h(S.h, (long)128 * Nn, 128, conv3_w, 128, S.xc + (long)128 * Nn, bxc, S.mean, S.rstd);

    self_att_h(S.xc + (long)128 * Nn, bxc, 128, sa_wq[3], sa_wk[3], sa_wv[3], sa_wc[3],
               S.h, (long)256 * Nn, S);
    conv_bn_h(S.h, (long)256 * Nn, 256, conv4_w, 256, S.xc + (long)256 * Nn, bxc, S.mean, S.rstd);

    conv_bn_h(S.xc, bxc, 512, conv5_w, 1024, S.x5, (long)1024 * Nn, S.mean, S.rstd);

    k_pool<<<Bb * 1024, 256>>>(S.x5, S.p);

    k_linear<<<(Bb * 512 + 7) / 8, 256>>>(S.p, lin1_w, lin1_b, S.f1, 2048, 512);
    k_bnf<<<2, 256>>>(S.f1, 512);
    k_linear<<<(Bb * 256 + 7) / 8, 256>>>(S.f1, lin2_w, lin2_b, S.f2, 512, 256);
    k_bnf<<<1, 256>>>(S.f2, 256);
    k_linear<<<(Bb * 40 + 7) / 8, 256>>>(S.f2, lin3_w, lin3_b, (float*)d_out, 256, 40);
}

// round 14
// speedup vs baseline: 1.2199x; 1.0023x over previous
#include <cuda_runtime.h>
#include <math.h>

#define Bb 8
#define Nn 2048
#define Kk 20

// ---------------- scratch (static device globals; no allocation) -------------
__device__ float g_pd[(size_t)Bb * Nn * Nn];     // 134 MB distance matrix
__device__ int   g_idx[Bb * Nn * Kk];            // knn indices
__device__ float g_sq[Bb * Nn];                  // squared norms
__device__ float g_h[(size_t)Bb * 256 * Nn];     // concat buffer (max 256 ch)
__device__ float g_att[(size_t)Bb * 128 * Nn];   // attention weighted-diff M
__device__ float g_qk[(size_t)Bb * 128 * Nn];    // Wqk @ X
__device__ float g_xt[(size_t)Bb * Nn * 128];    // X transposed [B,N,C]
__device__ float g_qkt[(size_t)Bb * Nn * 128];   // QK transposed [B,N,C]
__device__ float g_wqk[128 * 128];               // wk^T wq
__device__ float g_wcv[128 * 128];               // wc wv
__device__ float g_xc[(size_t)Bb * 512 * Nn];    // x1|x2|x3|x4 concat
__device__ float g_x5[(size_t)Bb * 1024 * Nn];   // conv5 output
__device__ float g_mean[1024];
__device__ float g_rstd[1024];
__device__ float g_p[Bb * 2048];
__device__ float g_f1[Bb * 512];
__device__ float g_f2[Bb * 256];

// ---------------- kernels ----------------------------------------------------

__global__ void k_sqnorm(const float* __restrict__ X, long bsx, int C,
                         float* __restrict__ sq) {
    int i = blockIdx.x * blockDim.x + threadIdx.x;
    if (i >= Bb * Nn) return;
    int b = i / Nn, n = i % Nn;
    const float* xp = X + (long)b * bsx + n;
    float s = 0.f;
    for (int c = 0; c < C; c++) { float v = xp[(long)c * Nn]; s += v * v; }
    sq[i] = s;
}

// -------- high-throughput fp32 GEMM --------
// Y[b][o][n] = sum_c A[b?][o][c] * X[b][c][n]
// dist!=0: Y = sq[o] + sq[n] - 2*acc, diag=INF (A is XT, O==Nn).
template<int BM, int TM>
__global__ void k_gemm(const float* __restrict__ A, long bsa, int lda,
                       const float* __restrict__ X, long bsx,
                       int C, int O,
                       float* __restrict__ Y, long bsy,
                       const float* __restrict__ sq, int dist) {
    const int BN = 128, TN = 8, KT = 16;
    __shared__ float sA[KT][BM + 4];
    __shared__ float sX[KT][BN];
    int b  = blockIdx.z;
    int n0 = blockIdx.x * BN;
    int o0 = blockIdx.y * BM;
    int t  = threadIdx.x;          // 256 threads
    int tx = t & 15, ty = t >> 4;
    const float* Ab = A + (long)b * bsa;
    const float* Xb = X + (long)b * bsx;

    float acc[TM][TN];
    #pragma unroll
    for (int i = 0; i < TM; i++)
        #pragma unroll
        for (int j = 0; j < TN; j++) acc[i][j] = 0.f;

    for (int k0 = 0; k0 < C; k0 += KT) {
        #pragma unroll
        for (int u = 0; u < (BM * KT) / 256; u++) {
            int e = t + u * 256;
            int c = e & 15, o = e >> 4;
            float v = 0.f;
            if (k0 + c < C && o0 + o < O) v = Ab[(long)(o0 + o) * lda + k0 + c];
            sA[c][o] = v;
        }
        #pragma unroll
        for (int u = 0; u < (KT * BN) / 256; u++) {
            int e = t + u * 256;
            int n = e & 127, c = e >> 7;
            float v = 0.f;
            if (k0 + c < C) v = Xb[(long)(k0 + c) * Nn + n0 + n];
            sX[c][n] = v;
        }
        __syncthreads();
        #pragma unroll
        for (int kk = 0; kk < KT; kk++) {
            float a[TM], x[TN];
            #pragma unroll
            for (int i = 0; i < TM; i += 4)
                *(float4*)&a[i] = *(const float4*)&sA[kk][ty * TM + i];
            #pragma unroll
            for (int j = 0; j < TN; j += 4)
                *(float4*)&x[j] = *(const float4*)&sX[kk][tx * TN + j];
            #pragma unroll
            for (int i = 0; i < TM; i++)
                #pragma unroll
                for (int j = 0; j < TN; j++) acc[i][j] += a[i] * x[j];
        }
        __syncthreads();
    }

    if (!dist) {
        #pragma unroll
        for (int i = 0; i < TM; i++) {
            int o = o0 + ty * TM + i;
            if (o >= O) continue;
            float* yp = Y + (long)b * bsy + (long)o * Nn + n0 + tx * TN;
            *(float4*)yp       = *(float4*)&acc[i][0];
            *(float4*)(yp + 4) = *(float4*)&acc[i][4];
        }
    } else {
        #pragma unroll
        for (int i = 0; i < TM; i++) {
            int o = o0 + ty * TM + i;
            float sqo = sq[b * Nn + o];
            float4 r[2];
            #pragma unroll
            for (int j = 0; j < TN; j++) {
                int n = n0 + tx * TN + j;
                float d = sqo + sq[b * Nn + n] - 2.f * acc[i][j];
                if (n == o) d = 3.0e38f;
                ((float*)r)[j] = d;
            }
            float* yp = Y + (long)b * bsy + (long)o * Nn + n0 + tx * TN;
            *(float4*)yp       = r[0];
            *(float4*)(yp + 4) = r[1];
        }
    }
}

// top-K smallest per row via 12-bit histogram select + small iterative argmin.
// key = order-preserving u32 of float; bin = key >> 20 (4096 bins).
// Find minimal bin B with cum >= K; candidates = keys with bin <= B (typ. ~100).
// Exact: final selection uses u64 (keybits << 11 | col) => lowest-index ties.
__global__ void k_topk(const float* __restrict__ pd, int* __restrict__ out) {
    __shared__ unsigned int hist[4096];
    __shared__ unsigned long long cand[2080];
    __shared__ unsigned int warpsum[8];
    __shared__ unsigned int s_B;
    __shared__ unsigned int s_nc;
    int row = blockIdx.x;                         // b*N + n
    int t = threadIdx.x, w = t >> 5, lane = t & 31;
    const unsigned FULL = 0xffffffffu;
    const float* p = pd + (long)row * Nn;

    #pragma unroll
    for (int i = 0; i < 16; i++) hist[t + 256 * i] = 0;
    if (t == 0) s_nc = 0;
    __syncthreads();

    // load 8 keys/thread (coalesced) + histogram
    unsigned key[8];
    #pragma unroll
    for (int j = 0; j < 8; j++) {
        unsigned bts = __float_as_uint(p[t + 256 * j]);
        bts = (bts & 0x80000000u) ? ~bts : (bts | 0x80000000u);   // order-preserving
        key[j] = bts;
        atomicAdd(&hist[bts >> 20], 1u);
    }
    __syncthreads();

    // block scan over per-thread partials (16 consecutive bins each)
    unsigned partial = 0;
    #pragma unroll
    for (int i = 0; i < 16; i++) partial += hist[t * 16 + i];
    unsigned incl = partial;
    #pragma unroll
    for (int off = 1; off < 32; off <<= 1) {
        unsigned v = __shfl_up_sync(FULL, incl, off);
        if (lane >= off) incl += v;
    }
    if (lane == 31) warpsum[w] = incl;
    __syncthreads();
    if (w == 0) {
        unsigned v = (lane < 8) ? warpsum[lane] : 0;
        #pragma unroll
        for (int off = 1; off < 8; off <<= 1) {
            unsigned u = __shfl_up_sync(FULL, v, off);
            if (lane >= off) v += u;
        }
        if (lane < 8) warpsum[lane] = v;
    }
    __syncthreads();
    if (w > 0) incl += warpsum[w - 1];
    unsigned excl = incl - partial;
    if (excl < Kk && Kk <= incl) {                // unique thread owns bin B
        unsigned cum = excl;
        for (int i = 0; i < 16; i++) {
            cum += hist[t * 16 + i];
            if (cum >= Kk) { s_B = t * 16 + i; break; }
        }
    }
    __syncthreads();
    unsigned B = s_B;

    // compact candidates (bin <= B); count(<B) <= 19 so >= 20 total, <= 2048
    #pragma unroll
    for (int j = 0; j < 8; j++) {
        if ((key[j] >> 20) <= B) {
            unsigned pos = atomicAdd(&s_nc, 1u);
            cand[pos] = ((unsigned long long)key[j] << 11) | (unsigned)(t + 256 * j);
        }
    }
    __syncthreads();
    int nc = (int)s_nc;

    // warp 0: 20 iterative argmin selections over the small candidate set
    if (w == 0) {
        for (int s = 0; s < Kk; s++) {
            unsigned long long mn = ~0ULL; int mi = -1;
            for (int i = lane; i < nc; i += 32) {
                unsigned long long v = cand[i];
                if (v < mn) { mn = v; mi = i; }
            }
            unsigned long long r = mn;
            #pragma unroll
            for (int off = 16; off; off >>= 1) {
                unsigned long long o = __shfl_xor_sync(FULL, r, off);
                r = o < r ? o : r;
            }
            if (lane == 0) out[(long)row * Kk + s] = (int)(r & 2047ULL);
            if (mn == r) cand[mi] = ~0ULL;        // unique owner clears
        }
    }
}

// transpose [B,C,N] -> [B,N,C]
__global__ void k_transpose(const float* __restrict__ X, long bsx, int C,
                            float* __restrict__ XT) {
    __shared__ float tile[32][33];
    int b = blockIdx.z;
    int n0 = blockIdx.x * 32, c0 = blockIdx.y * 32;
    for (int i = threadIdx.y; i < 32; i += 8) {
        int c = c0 + i;
        tile[i][threadIdx.x] = (c < C) ? X[(long)b * bsx + (long)c * Nn + n0 + threadIdx.x] : 0.f;
    }
    __syncthreads();
    for (int i = threadIdx.y; i < 32; i += 8) {
        int n = n0 + i, c = c0 + threadIdx.x;
        if (c < C) XT[((long)b * Nn + n) * C + c] = tile[threadIdx.x][i];
    }
}

// Wqk[i][j] = sum_e wk[e][i] * wq[e][j]
__global__ void k_wqk(const float* __restrict__ wk, const float* __restrict__ wq,
                      float* __restrict__ out, int C) {
    int j = blockIdx.x * 16 + threadIdx.x;
    int i = blockIdx.y * 16 + threadIdx.y;
    if (i >= C || j >= C) return;
    float a = 0.f;
    for (int e = 0; e < C; e++) a += wk[e * C + i] * wq[e * C + j];
    out[i * C + j] = a;
}

// Wcv[i][j] = sum_v wc[i][v] * wv[v][j]
__global__ void k_wcv(const float* __restrict__ wc, const float* __restrict__ wv,
                      float* __restrict__ out, int C) {
    int j = blockIdx.x * 16 + threadIdx.x;
    int i = blockIdx.y * 16 + threadIdx.y;
    if (i >= C || j >= C) return;
    float a = 0.f;
    for (int v = 0; v < C; v++) a += wc[i * C + v] * wv[v * C + j];
    out[i * C + j] = a;
}

// attention gather/softmax: one warp per point, 32 points per block
__global__ void k_attn2(const float* __restrict__ XT, const float* __restrict__ QKT,
                        int C, const int* __restrict__ idx,
                        float* __restrict__ M, long bsm) {
    __shared__ float s_m[128][33];
    const unsigned FULL = 0xffffffffu;
    int w = threadIdx.x >> 5, lane = threadIdx.x & 31;
    int pt = blockIdx.x * 32 + w;
    int b = pt / Nn;
    int n0 = (blockIdx.x & 63) * 32;
    int NR = (C + 31) >> 5;

    float qk[4], f[4];
    const float* qrow = QKT + (long)pt * C;
    const float* frow = XT + (long)pt * C;
    #pragma unroll
    for (int r = 0; r < 4; r++) {
        int c = lane + 32 * r;
        bool ok = (r < NR) && (c < C);
        qk[r] = ok ? qrow[c] : 0.f;
        f[r]  = ok ? frow[c] : 0.f;
    }
    const int* ip = idx + (long)pt * Kk;

    float myscore = 0.f;
    for (int j = 0; j < Kk; j++) {
        int ij = ip[j];
        const float* nrow = XT + ((long)b * Nn + ij) * C;
        float p = 0.f;
        #pragma unroll
        for (int r = 0; r < 4; r++) {
            int c = lane + 32 * r;
            if (r < NR && c < C) p += qk[r] * nrow[c];
        }
        #pragma unroll
        for (int off = 16; off > 0; off >>= 1) p += __shfl_xor_sync(FULL, p, off);
        if (lane == j) myscore = p;
    }
    float scale = rsqrtf((float)C);
    float val = (lane < Kk) ? myscore * scale : -3.0e38f;
    float mx = val;
    #pragma unroll
    for (int off = 16; off > 0; off >>= 1) mx = fmaxf(mx, __shfl_xor_sync(FULL, mx, off));
    float e = (lane < Kk) ? expf(val - mx) : 0.f;
    float sm = e;
    #pragma unroll
    for (int off = 16; off > 0; off >>= 1) sm += __shfl_xor_sync(FULL, sm, off);
    float wme = e / sm;

    float m[4] = {0.f, 0.f, 0.f, 0.f};
    for (int j = 0; j < Kk; j++) {
        float wj = __shfl_sync(FULL, wme, j);
        int ij = ip[j];
        const float* nrow = XT + ((long)b * Nn + ij) * C;
        #pragma unroll
        for (int r = 0; r < 4; r++) {
            int c = lane + 32 * r;
            if (r < NR && c < C) m[r] += wj * nrow[c];
        }
    }
    #pragma unroll
    for (int r = 0; r < 4; r++) m[r] -= f[r];

    #pragma unroll
    for (int r = 0; r < 4; r++) {
        int c = lane + 32 * r;
        if (r < NR && c < C) s_m[c][w] = m[r];
    }
    __syncthreads();
    int t = threadIdx.x;
    for (int e2 = t; e2 < C * 32; e2 += 1024) {
        int c = e2 >> 5, p2 = e2 & 31;
        M[(long)b * bsm + (long)c * Nn + n0 + p2] = s_m[c][p2];
    }
}

// per-channel batch stats over (B,N)
__global__ void k_bnstats(const float* __restrict__ Y, long bsy,
                          float* __restrict__ mean, float* __restrict__ rstd) {
    int o = blockIdx.x;
    int t = threadIdx.x;
    float s1 = 0.f, s2 = 0.f;
    for (int i = t; i < Bb * Nn; i += 256) {
        int b = i / Nn, n = i % Nn;
        float v = Y[(long)b * bsy + (long)o * Nn + n];
        s1 += v; s2 += v * v;
    }
    __shared__ float r1[256], r2[256];
    r1[t] = s1; r2[t] = s2;
    __syncthreads();
    for (int off = 128; off > 0; off >>= 1) {
        if (t < off) { r1[t] += r1[t + off]; r2[t] += r2[t + off]; }
        __syncthreads();
    }
    if (t == 0) {
        float m = r1[0] / (float)(Bb * Nn);
        float v = r2[0] / (float)(Bb * Nn) - m * m;
        mean[o] = m;
        rstd[o] = rsqrtf(v + 1e-5f);
    }
}

__global__ void k_bnapply(float* __restrict__ Y, long bsy, int O,
                          const float* __restrict__ mean, const float* __restrict__ rstd) {
    long total = (long)Bb * O * Nn;
    for (long i = (long)blockIdx.x * blockDim.x + threadIdx.x; i < total;
         i += (long)gridDim.x * blockDim.x) {
        int n = (int)(i % Nn);
        long bo = i / Nn;
        int o = (int)(bo % O);
        int b = (int)(bo / O);
        float* p = Y + (long)b * bsy + (long)o * Nn + n;
        float v = (*p - mean[o]) * rstd[o];
        *p = v >= 0.f ? v : 0.2f * v;
    }
}

__global__ void k_copy(const float* __restrict__ X, long bsx,
                       float* __restrict__ D, long bsd, int C) {
    long total = (long)Bb * C * Nn;
    for (long i = (long)blockIdx.x * blockDim.x + threadIdx.x; i < total;
         i += (long)gridDim.x * blockDim.x) {
        int n = (int)(i % Nn);
        long bc = i / Nn;
        int c = (int)(bc % C);
        int b = (int)(bc / C);
        D[(long)b * bsd + (long)c * Nn + n] = X[(long)b * bsx + (long)c * Nn + n];
    }
}

__global__ void k_pool(const float* __restrict__ X5, float* __restrict__ p) {
    int bc = blockIdx.x;
    int b = bc / 1024, c = bc % 1024;
    const float* xp = X5 + ((long)b * 1024 + c) * Nn;
    int t = threadIdx.x;
    float mx = -3e38f, sm = 0.f;
    for (int n = t; n < Nn; n += 256) { float v = xp[n]; mx = fmaxf(mx, v); sm += v; }
    __shared__ float smx[256], ssm[256];
    smx[t] = mx; ssm[t] = sm;
    __syncthreads();
    for (int off = 128; off > 0; off >>= 1) {
        if (t < off) { smx[t] = fmaxf(smx[t], smx[t + off]); ssm[t] += ssm[t + off]; }
        __syncthreads();
    }
    if (t == 0) {
        p[b * 2048 + c]        = smx[0];
        p[b * 2048 + 1024 + c] = ssm[0] / (float)Nn;
    }
}

__global__ void k_linear(const float* __restrict__ in, const float* __restrict__ W,
                         const float* __restrict__ bias, float* __restrict__ out,
                         int I, int O) {
    int w = (blockIdx.x * blockDim.x + threadIdx.x) >> 5;
    int lane = threadIdx.x & 31;
    if (w >= Bb * O) return;
    int b = w / O, o = w % O;
    const float* ip = in + (long)b * I;
    const float* wp = W + (long)o * I;
    float a = 0.f;
    for (int i = lane; i < I; i += 32) a += ip[i] * wp[i];
    for (int off = 16; off > 0; off >>= 1) a += __shfl_down_sync(0xffffffffu, a, off);
    if (lane == 0) out[w] = a + bias[o];
}

__global__ void k_bnf(float* __restrict__ Y, int O) {
    int o = blockIdx.x * blockDim.x + threadIdx.x;
    if (o >= O) return;
    float s1 = 0.f, s2 = 0.f;
    for (int b = 0; b < Bb; b++) { float v = Y[b * O + o]; s1 += v; s2 += v * v; }
    float m = s1 / (float)Bb;
    float v = s2 / (float)Bb - m * m;
    float r = rsqrtf(v + 1e-5f);
    for (int b = 0; b < Bb; b++) {
        float u = (Y[b * O + o] - m) * r;
        Y[b * O + o] = u >= 0.f ? u : 0.2f * u;
    }
}

// ---------------- host orchestration ----------------------------------------

static void gemm_h(const float* A, long bsa, int lda, const float* X, long bsx,
                   int C, int O, float* Y, long bsy, const float* sq, int dist) {
    if (O % 128 == 0) {
        dim3 g(Nn / 128, O / 128, Bb);
        k_gemm<128, 8><<<g, 256>>>(A, bsa, lda, X, bsx, C, O, Y, bsy, sq, dist);
    } else {
        dim3 g(Nn / 128, (O + 63) / 64, Bb);
        k_gemm<64, 4><<<g, 256>>>(A, bsa, lda, X, bsx, C, O, Y, bsy, sq, dist);
    }
}

struct Scratch {
    float *pd, *sq, *att, *qk, *xt, *qkt, *wqk, *wcv, *h, *xc, *x5, *mean, *rstd, *p, *f1, *f2;
    int* idx;
};

static void conv_bn_h(const float* X, long bsx, int C, const float* W, int O,
                      float* Y, long bsy, float* mean, float* rstd) {
    gemm_h(W, 0, C, X, bsx, C, O, Y, bsy, nullptr, 0);
    k_bnstats<<<O, 256>>>(Y, bsy, mean, rstd);
    long total = (long)Bb * O * Nn;
    k_bnapply<<<(int)((total + 255) / 256), 256>>>(Y, bsy, O, mean, rstd);
}

static void self_att_h(const float* X, long bsx, int C,
                       const float* wq, const float* wk, const float* wv, const float* wc,
                       float* H, long bsh, const Scratch& S) {
    k_sqnorm<<<(Bb * Nn + 255) / 256, 256>>>(X, bsx, C, S.sq);

    // transpose X -> XT [B,N,C]
    dim3 tg(Nn / 32, (C + 31) / 32, Bb);
    k_transpose<<<tg, dim3(32, 8)>>>(X, bsx, C, S.xt);

    // dist = GEMM(A=XT, X) with dist epilogue
    gemm_h(S.xt, (long)Nn * C, C, X, bsx, C, Nn, S.pd, (long)Nn * Nn, S.sq, 1);
    k_topk<<<Bb * Nn, 256>>>(S.pd, S.idx);

    // Wqk = wk^T wq ; QK = Wqk @ X ; transpose -> QKT
    dim3 sg((C + 15) / 16, (C + 15) / 16);
    k_wqk<<<sg, dim3(16, 16)>>>(wk, wq, S.wqk, C);
    gemm_h(S.wqk, 0, C, X, bsx, C, C, S.qk, (long)C * Nn, nullptr, 0);
    k_transpose<<<tg, dim3(32, 8)>>>(S.qk, (long)C * Nn, C, S.qkt);

    // gather + softmax + weighted diff -> M
    k_attn2<<<Bb * Nn / 32, 1024>>>(S.xt, S.qkt, C, S.idx, S.att, (long)C * Nn);

    // res = conv_bn(Wcv @ M)
    k_wcv<<<sg, dim3(16, 16)>>>(wc, wv, S.wcv, C);
    conv_bn_h(S.att, (long)C * Nn, C, S.wcv, C, H, bsh, S.mean, S.rstd);

    // concat raw x into channels [C, 2C)
    long total = (long)Bb * C * Nn;
    k_copy<<<(int)((total + 255) / 256), 256>>>(X, bsx, H + (long)C * Nn, bsh, C);
}

extern "C" void kernel_launch(void* const* d_in, const int* in_sizes, int n_in,
                              void* d_out, int out_size) {
    const float* x = (const float*)d_in[0];
    const float* sa_wq[4] = {(const float*)d_in[1],  (const float*)d_in[5],
                             (const float*)d_in[9],  (const float*)d_in[13]};
    const float* sa_wk[4] = {(const float*)d_in[2],  (const float*)d_in[6],
                             (const float*)d_in[10], (const float*)d_in[14]};
    const float* sa_wv[4] = {(const float*)d_in[3],  (const float*)d_in[7],
                             (const float*)d_in[11], (const float*)d_in[15]};
    const float* sa_wc[4] = {(const float*)d_in[4],  (const float*)d_in[8],
                             (const float*)d_in[12], (const float*)d_in[16]};
    const float* conv1_w = (const float*)d_in[17];
    const float* conv2_w = (const float*)d_in[18];
    const float* conv3_w = (const float*)d_in[19];
    const float* conv4_w = (const float*)d_in[20];
    const float* conv5_w = (const float*)d_in[21];
    const float* lin1_w = (const float*)d_in[22];
    const float* lin1_b = (const float*)d_in[23];
    const float* lin2_w = (const float*)d_in[24];
    const float* lin2_b = (const float*)d_in[25];
    const float* lin3_w = (const float*)d_in[26];
    const float* lin3_b = (const float*)d_in[27];

    Scratch S;
    cudaGetSymbolAddress((void**)&S.pd,   g_pd);
    cudaGetSymbolAddress((void**)&S.idx,  g_idx);
    cudaGetSymbolAddress((void**)&S.sq,   g_sq);
    cudaGetSymbolAddress((void**)&S.h,    g_h);
    cudaGetSymbolAddress((void**)&S.att,  g_att);
    cudaGetSymbolAddress((void**)&S.qk,   g_qk);
    cudaGetSymbolAddress((void**)&S.xt,   g_xt);
    cudaGetSymbolAddress((void**)&S.qkt,  g_qkt);
    cudaGetSymbolAddress((void**)&S.wqk,  g_wqk);
    cudaGetSymbolAddress((void**)&S.wcv,  g_wcv);
    cudaGetSymbolAddress((void**)&S.xc,   g_xc);
    cudaGetSymbolAddress((void**)&S.x5,   g_x5);
    cudaGetSymbolAddress((void**)&S.mean, g_mean);
    cudaGetSymbolAddress((void**)&S.rstd, g_rstd);
    cudaGetSymbolAddress((void**)&S.p,    g_p);
    cudaGetSymbolAddress((void**)&S.f1,   g_f1);
    cudaGetSymbolAddress((void**)&S.f2,   g_f2);

    const long bxc = (long)512 * Nn;

    self_att_h(x, (long)3 * Nn, 3, sa_wq[0], sa_wk[0], sa_wv[0], sa_wc[0],
               S.h, (long)6 * Nn, S);
    conv_bn_h(S.h, (long)6 * Nn, 6, conv1_w, 64, S.xc, bxc, S.mean, S.rstd);

    self_att_h(S.xc, bxc, 64, sa_wq[1], sa_wk[1], sa_wv[1], sa_wc[1],
               S.h, (long)128 * Nn, S);
    conv_bn_h(S.h, (long)128 * Nn, 128, conv2_w, 64, S.xc + (long)64 * Nn, bxc, S.mean, S.rstd);

    self_att_h(S.xc + (long)64 * Nn, bxc, 64, sa_wq[2], sa_wk[2], sa_wv[2], sa_wc[2],
               S.h, (long)128 * Nn, S);
    conv_bn_h(S.h, (long)128 * Nn, 128, conv3_w, 128, S.xc + (long)128 * Nn, bxc, S.mean, S.rstd);

    self_att_h(S.xc + (long)128 * Nn, bxc, 128, sa_wq[3], sa_wk[3], sa_wv[3], sa_wc[3],
               S.h, (long)256 * Nn, S);
    conv_bn_h(S.h, (long)256 * Nn, 256, conv4_w, 256, S.xc + (long)256 * Nn, bxc, S.mean, S.rstd);

    conv_bn_h(S.xc, bxc, 512, conv5_w, 1024, S.x5, (long)1024 * Nn, S.mean, S.rstd);

    k_pool<<<Bb * 1024, 256>>>(S.x5, S.p);

    k_linear<<<(Bb * 512 + 7) / 8, 256>>>(S.p, lin1_w, lin1_b, S.f1, 2048, 512);
    k_bnf<<<2, 256>>>(S.f1, 512);
    k_linear<<<(Bb * 256 + 7) / 8, 256>>>(S.f1, lin2_w, lin2_b, S.f2, 512, 256);
    k_bnf<<<1, 256>>>(S.f2, 256);
    k_linear<<<(Bb * 40 + 7) / 8, 256>>>(S.f2, lin3_w, lin3_b, (float*)d_out, 256, 40);
}

// round 15
// speedup vs baseline: 1.5526x; 1.2727x over previous
#include <cuda_runtime.h>
#include <math.h>

#define Bb 8
#define Nn 2048
#define Kk 20

// ---------------- scratch (static device globals; no allocation) -------------
__device__ float g_pd[(size_t)Bb * Nn * Nn];     // 134 MB distance matrix
__device__ int   g_idx[Bb * Nn * Kk];            // knn indices
__device__ float g_sq[Bb * Nn];                  // squared norms
__device__ float g_h[(size_t)Bb * 256 * Nn];     // concat buffer (max 256 ch)
__device__ float g_att[(size_t)Bb * 128 * Nn];   // attention weighted-diff M
__device__ float g_qk[(size_t)Bb * 128 * Nn];    // Wqk @ X
__device__ float g_xt[(size_t)Bb * Nn * 128];    // X transposed [B,N,C]
__device__ float g_qkt[(size_t)Bb * Nn * 128];   // QK transposed [B,N,C]
__device__ float g_wqk[128 * 128];               // wk^T wq
__device__ float g_wcv[128 * 128];               // wc wv
__device__ float g_xc[(size_t)Bb * 512 * Nn];    // x1|x2|x3|x4 concat
__device__ float g_x5[(size_t)Bb * 1024 * Nn];   // conv5 output
__device__ float g_mean[1024];
__device__ float g_rstd[1024];
__device__ float g_p[Bb * 2048];
__device__ float g_f1[Bb * 512];
__device__ float g_f2[Bb * 256];

// ---------------- kernels ----------------------------------------------------

__global__ void k_sqnorm(const float* __restrict__ X, long bsx, int C,
                         float* __restrict__ sq) {
    int i = blockIdx.x * blockDim.x + threadIdx.x;
    if (i >= Bb * Nn) return;
    int b = i / Nn, n = i % Nn;
    const float* xp = X + (long)b * bsx + n;
    float s = 0.f;
    for (int c = 0; c < C; c++) { float v = xp[(long)c * Nn]; s += v * v; }
    sq[i] = s;
}

// -------- symmetric distance GEMM (double-buffered, upper-triangular tiles) --
// Computes pd[b][o][n] = sq[o]+sq[n]-2*X_o.X_n for tile pairs (a<=b), mirrors
// off-diagonal tiles via smem transpose staging. diag = INF.
__global__ void k_dist(const float* __restrict__ X, long bsx, int C,
                       const float* __restrict__ sq, float* __restrict__ pd) {
    const int KT = 16;
    __shared__ float sA[2][KT][132];
    __shared__ float sX[2][KT][128];
    int bz = blockIdx.z;
    // triangular decode: blockIdx.x in [0,136) -> (a,b), a<=b
    int id = blockIdx.x, a = 0;
    while (id >= 16 - a) { id -= 16 - a; a++; }
    int bt = a + id;
    int o0 = a * 128, n0 = bt * 128;
    int t = threadIdx.x, tx = t & 15, ty = t >> 4;
    const float* Xb = X + (long)bz * bsx;

    float acc[8][8];
    #pragma unroll
    for (int i = 0; i < 8; i++)
        #pragma unroll
        for (int j = 0; j < 8; j++) acc[i][j] = 0.f;

    // prologue: tile 0 -> buf 0
    #pragma unroll
    for (int u = 0; u < 8; u++) {
        int e = t + u * 256;
        int n = e & 127, c = e >> 7;
        float va = 0.f, vx = 0.f;
        if (c < C) {
            va = Xb[(long)c * Nn + o0 + n];
            vx = Xb[(long)c * Nn + n0 + n];
        }
        sA[0][c][n] = va;
        sX[0][c][n] = vx;
    }
    __syncthreads();
    int buf = 0;
    for (int k0 = 0; k0 < C; k0 += KT) {
        int nx = k0 + KT;
        if (nx < C) {
            #pragma unroll
            for (int u = 0; u < 8; u++) {
                int e = t + u * 256;
                int n = e & 127, c = e >> 7;
                float va = 0.f, vx = 0.f;
                if (nx + c < C) {
                    va = Xb[(long)(nx + c) * Nn + o0 + n];
                    vx = Xb[(long)(nx + c) * Nn + n0 + n];
                }
                sA[buf ^ 1][c][n] = va;
                sX[buf ^ 1][c][n] = vx;
            }
        }
        #pragma unroll
        for (int kk = 0; kk < KT; kk++) {
            float av[8], xv[8];
            #pragma unroll
            for (int i = 0; i < 8; i += 4)
                *(float4*)&av[i] = *(const float4*)&sA[buf][kk][ty * 8 + i];
            #pragma unroll
            for (int j = 0; j < 8; j += 4)
                *(float4*)&xv[j] = *(const float4*)&sX[buf][kk][tx * 8 + j];
            #pragma unroll
            for (int i = 0; i < 8; i++)
                #pragma unroll
                for (int j = 0; j < 8; j++) acc[i][j] += av[i] * xv[j];
        }
        __syncthreads();
        buf ^= 1;
    }

    float sqo[8], sqn[8];
    #pragma unroll
    for (int i = 0; i < 8; i++) sqo[i] = sq[bz * Nn + o0 + ty * 8 + i];
    #pragma unroll
    for (int j = 0; j < 8; j++) sqn[j] = sq[bz * Nn + n0 + tx * 8 + j];

    // normal write: pd[o][n]
    #pragma unroll
    for (int i = 0; i < 8; i++) {
        int o = o0 + ty * 8 + i;
        float4 r[2];
        #pragma unroll
        for (int j = 0; j < 8; j++) {
            int n = n0 + tx * 8 + j;
            float d = sqo[i] + sqn[j] - 2.f * acc[i][j];
            if (n == o) d = 3.0e38f;
            ((float*)r)[j] = d;
        }
        float* yp = pd + ((long)bz * Nn + o) * Nn + n0 + tx * 8;
        *(float4*)yp       = r[0];
        *(float4*)(yp + 4) = r[1];
    }

    // mirror write: pd[n][o] via 16-row staging chunks
    if (a != bt) {
        float* stage = &sA[0][0][0];   // 2048 floats, smem free after k-loop sync
        int mych = tx >> 1;
        for (int ch = 0; ch < 8; ch++) {
            __syncthreads();
            if (ch == mych) {
                #pragma unroll
                for (int j = 0; j < 8; j++) {
                    int nn = (tx & 1) * 8 + j;
                    #pragma unroll
                    for (int i = 0; i < 8; i++) {
                        float d = sqo[i] + sqn[j] - 2.f * acc[i][j];
                        stage[nn * 128 + ty * 8 + i] = d;
                    }
                }
            }
            __syncthreads();
            int nn = t >> 4, oo = (t & 15) * 8;
            float* yp = pd + ((long)bz * Nn + (n0 + ch * 16 + nn)) * Nn + o0 + oo;
            *(float4*)yp       = *(float4*)&stage[nn * 128 + oo];
            *(float4*)(yp + 4) = *(float4*)&stage[nn * 128 + oo + 4];
        }
    }
}

// -------- conv 1x1 GEMM (double-buffered) --------
// Y[b][o][n] = sum_c W[o][c] * X[b][c][n]
template<int BM, int TM>
__global__ void k_gemm(const float* __restrict__ A, int lda,
                       const float* __restrict__ X, long bsx,
                       int C, int O,
                       float* __restrict__ Y, long bsy) {
    const int BN = 128, TN = 8, KT = 16;
    __shared__ float sA[2][KT][BM + 4];
    __shared__ float sX[2][KT][BN];
    int b  = blockIdx.z;
    int n0 = blockIdx.x * BN;
    int o0 = blockIdx.y * BM;
    int t  = threadIdx.x;          // 256 threads
    int tx = t & 15, ty = t >> 4;
    const float* Xb = X + (long)b * bsx;

    float acc[TM][TN];
    #pragma unroll
    for (int i = 0; i < TM; i++)
        #pragma unroll
        for (int j = 0; j < TN; j++) acc[i][j] = 0.f;

    // prologue
    #pragma unroll
    for (int u = 0; u < (BM * KT) / 256; u++) {
        int e = t + u * 256;
        int c = e & 15, o = e >> 4;
        float v = 0.f;
        if (c < C && o0 + o < O) v = A[(long)(o0 + o) * lda + c];
        sA[0][c][o] = v;
    }
    #pragma unroll
    for (int u = 0; u < (KT * BN) / 256; u++) {
        int e = t + u * 256;
        int n = e & 127, c = e >> 7;
        sX[0][c][n] = (c < C) ? Xb[(long)c * Nn + n0 + n] : 0.f;
    }
    __syncthreads();
    int buf = 0;
    for (int k0 = 0; k0 < C; k0 += KT) {
        int nx = k0 + KT;
        if (nx < C) {
            #pragma unroll
            for (int u = 0; u < (BM * KT) / 256; u++) {
                int e = t + u * 256;
                int c = e & 15, o = e >> 4;
                float v = 0.f;
                if (nx + c < C && o0 + o < O) v = A[(long)(o0 + o) * lda + nx + c];
                sA[buf ^ 1][c][o] = v;
            }
            #pragma unroll
            for (int u = 0; u < (KT * BN) / 256; u++) {
                int e = t + u * 256;
                int n = e & 127, c = e >> 7;
                sX[buf ^ 1][c][n] = (nx + c < C) ? Xb[(long)(nx + c) * Nn + n0 + n] : 0.f;
            }
        }
        #pragma unroll
        for (int kk = 0; kk < KT; kk++) {
            float av[TM], xv[TN];
            #pragma unroll
            for (int i = 0; i < TM; i += 4)
                *(float4*)&av[i] = *(const float4*)&sA[buf][kk][ty * TM + i];
            #pragma unroll
            for (int j = 0; j < TN; j += 4)
                *(float4*)&xv[j] = *(const float4*)&sX[buf][kk][tx * TN + j];
            #pragma unroll
            for (int i = 0; i < TM; i++)
                #pragma unroll
                for (int j = 0; j < TN; j++) acc[i][j] += av[i] * xv[j];
        }
        __syncthreads();
        buf ^= 1;
    }

    #pragma unroll
    for (int i = 0; i < TM; i++) {
        int o = o0 + ty * TM + i;
        if (o >= O) continue;
        float* yp = Y + (long)b * bsy + (long)o * Nn + n0 + tx * TN;
        *(float4*)yp       = *(float4*)&acc[i][0];
        *(float4*)(yp + 4) = *(float4*)&acc[i][4];
    }
}

// top-K smallest per row via 12-bit histogram select.
// bins < B  -> guaranteed top-K, emitted directly (set-invariant order).
// bin == B  -> u32 candidates (key low 20 bits : col), exact iterative argmin
//              for the remaining r slots (lowest-index tie-break preserved).
__global__ void k_topk(const float* __restrict__ pd, int* __restrict__ out) {
    __shared__ unsigned int hist[4096];
    __shared__ unsigned int cand[2048];
    __shared__ unsigned int warpsum[8];
    __shared__ unsigned int s_B, s_r, s_no, s_nc;
    int row = blockIdx.x;                         // b*N + n
    int t = threadIdx.x, w = t >> 5, lane = t & 31;
    const unsigned FULL = 0xffffffffu;
    const float* p = pd + (long)row * Nn;

    #pragma unroll
    for (int i = 0; i < 16; i++) hist[t + 256 * i] = 0;
    if (t == 0) { s_no = 0; s_nc = 0; }
    __syncthreads();

    unsigned key[8];
    #pragma unroll
    for (int j = 0; j < 8; j++) {
        unsigned bts = __float_as_uint(p[t + 256 * j]);
        bts = (bts & 0x80000000u) ? ~bts : (bts | 0x80000000u);   // order-preserving
        key[j] = bts;
        atomicAdd(&hist[bts >> 20], 1u);
    }
    __syncthreads();

    // block scan over per-thread partials (16 consecutive bins each)
    unsigned partial = 0;
    #pragma unroll
    for (int i = 0; i < 16; i++) partial += hist[t * 16 + i];
    unsigned incl = partial;
    #pragma unroll
    for (int off = 1; off < 32; off <<= 1) {
        unsigned v = __shfl_up_sync(FULL, incl, off);
        if (lane >= off) incl += v;
    }
    if (lane == 31) warpsum[w] = incl;
    __syncthreads();
    if (w == 0) {
        unsigned v = (lane < 8) ? warpsum[lane] : 0;
        #pragma unroll
        for (int off = 1; off < 8; off <<= 1) {
            unsigned u = __shfl_up_sync(FULL, v, off);
            if (lane >= off) v += u;
        }
        if (lane < 8) warpsum[lane] = v;
    }
    __syncthreads();
    if (w > 0) incl += warpsum[w - 1];
    unsigned excl = incl - partial;
    if (excl < Kk && Kk <= incl) {                // unique thread owns bin B
        unsigned cum = excl;
        for (int i = 0; i < 16; i++) {
            unsigned h = hist[t * 16 + i];
            cum += h;
            if (cum >= Kk) {
                s_B = t * 16 + i;
                s_r = Kk - (cum - h);             // slots to fill from bin B
                break;
            }
        }
    }
    __syncthreads();
    unsigned B = s_B;

    // compact: bins<B direct out; bin==B -> candidates
    #pragma unroll
    for (int j = 0; j < 8; j++) {
        unsigned bin = key[j] >> 20;
        if (bin < B) {
            unsigned pos = atomicAdd(&s_no, 1u);
            out[(long)row * Kk + pos] = t + 256 * j;
        } else if (bin == B) {
            unsigned pos = atomicAdd(&s_nc, 1u);
            cand[pos] = ((key[j] & 0xFFFFFu) << 11) | (unsigned)(t + 256 * j);
        }
    }
    __syncthreads();
    int nc = (int)s_nc, rr = (int)s_r, base = Kk - rr;

    if (w == 0) {
        for (int s = 0; s < rr; s++) {
            unsigned mn = 0xFFFFFFFFu; int mi = -1;
            for (int i = lane; i < nc; i += 32) {
                unsigned v = cand[i];
                if (v < mn) { mn = v; mi = i; }
            }
            unsigned r = mn;
            #pragma unroll
            for (int off = 16; off; off >>= 1) {
                unsigned o = __shfl_xor_sync(FULL, r, off);
                r = o < r ? o : r;
            }
            if (lane == 0) out[(long)row * Kk + base + s] = (int)(r & 2047u);
            if (mn == r && mi >= 0) cand[mi] = 0xFFFFFFFFu;   // unique owner clears
        }
    }
}

// transpose [B,C,N] -> [B,N,C]
__global__ void k_transpose(const float* __restrict__ X, long bsx, int C,
                            float* __restrict__ XT) {
    __shared__ float tile[32][33];
    int b = blockIdx.z;
    int n0 = blockIdx.x * 32, c0 = blockIdx.y * 32;
    for (int i = threadIdx.y; i < 32; i += 8) {
        int c = c0 + i;
        tile[i][threadIdx.x] = (c < C) ? X[(long)b * bsx + (long)c * Nn + n0 + threadIdx.x] : 0.f;
    }
    __syncthreads();
    for (int i = threadIdx.y; i < 32; i += 8) {
        int n = n0 + i, c = c0 + threadIdx.x;
        if (c < C) XT[((long)b * Nn + n) * C + c] = tile[threadIdx.x][i];
    }
}

// Wqk[i][j] = sum_e wk[e][i] * wq[e][j]
__global__ void k_wqk(const float* __restrict__ wk, const float* __restrict__ wq,
                      float* __restrict__ out, int C) {
    int j = blockIdx.x * 16 + threadIdx.x;
    int i = blockIdx.y * 16 + threadIdx.y;
    if (i >= C || j >= C) return;
    float a = 0.f;
    for (int e = 0; e < C; e++) a += wk[e * C + i] * wq[e * C + j];
    out[i * C + j] = a;
}

// Wcv[i][j] = sum_v wc[i][v] * wv[v][j]
__global__ void k_wcv(const float* __restrict__ wc, const float* __restrict__ wv,
                      float* __restrict__ out, int C) {
    int j = blockIdx.x * 16 + threadIdx.x;
    int i = blockIdx.y * 16 + threadIdx.y;
    if (i >= C || j >= C) return;
    float a = 0.f;
    for (int v = 0; v < C; v++) a += wc[i * C + v] * wv[v * C + j];
    out[i * C + j] = a;
}

// attention gather/softmax: one warp per point, 32 points per block
__global__ void k_attn2(const float* __restrict__ XT, const float* __restrict__ QKT,
                        int C, const int* __restrict__ idx,
                        float* __restrict__ M, long bsm) {
    __shared__ float s_m[128][33];
    const unsigned FULL = 0xffffffffu;
    int w = threadIdx.x >> 5, lane = threadIdx.x & 31;
    int pt = blockIdx.x * 32 + w;
    int b = pt / Nn;
    int n0 = (blockIdx.x & 63) * 32;
    int NR = (C + 31) >> 5;

    float qk[4], f[4];
    const float* qrow = QKT + (long)pt * C;
    const float* frow = XT + (long)pt * C;
    #pragma unroll
    for (int r = 0; r < 4; r++) {
        int c = lane + 32 * r;
        bool ok = (r < NR) && (c < C);
        qk[r] = ok ? qrow[c] : 0.f;
        f[r]  = ok ? frow[c] : 0.f;
    }
    const int* ip = idx + (long)pt * Kk;

    float myscore = 0.f;
    for (int j = 0; j < Kk; j++) {
        int ij = ip[j];
        const float* nrow = XT + ((long)b * Nn + ij) * C;
        float p = 0.f;
        #pragma unroll
        for (int r = 0; r < 4; r++) {
            int c = lane + 32 * r;
            if (r < NR && c < C) p += qk[r] * nrow[c];
        }
        #pragma unroll
        for (int off = 16; off > 0; off >>= 1) p += __shfl_xor_sync(FULL, p, off);
        if (lane == j) myscore = p;
    }
    float scale = rsqrtf((float)C);
    float val = (lane < Kk) ? myscore * scale : -3.0e38f;
    float mx = val;
    #pragma unroll
    for (int off = 16; off > 0; off >>= 1) mx = fmaxf(mx, __shfl_xor_sync(FULL, mx, off));
    float e = (lane < Kk) ? expf(val - mx) : 0.f;
    float sm = e;
    #pragma unroll
    for (int off = 16; off > 0; off >>= 1) sm += __shfl_xor_sync(FULL, sm, off);
    float wme = e / sm;

    float m[4] = {0.f, 0.f, 0.f, 0.f};
    for (int j = 0; j < Kk; j++) {
        float wj = __shfl_sync(FULL, wme, j);
        int ij = ip[j];
        const float* nrow = XT + ((long)b * Nn + ij) * C;
        #pragma unroll
        for (int r = 0; r < 4; r++) {
            int c = lane + 32 * r;
            if (r < NR && c < C) m[r] += wj * nrow[c];
        }
    }
    #pragma unroll
    for (int r = 0; r < 4; r++) m[r] -= f[r];

    #pragma unroll
    for (int r = 0; r < 4; r++) {
        int c = lane + 32 * r;
        if (r < NR && c < C) s_m[c][w] = m[r];
    }
    __syncthreads();
    int t = threadIdx.x;
    for (int e2 = t; e2 < C * 32; e2 += 1024) {
        int c = e2 >> 5, p2 = e2 & 31;
        M[(long)b * bsm + (long)c * Nn + n0 + p2] = s_m[c][p2];
    }
}

// per-channel batch stats over (B,N)
__global__ void k_bnstats(const float* __restrict__ Y, long bsy,
                          float* __restrict__ mean, float* __restrict__ rstd) {
    int o = blockIdx.x;
    int t = threadIdx.x;
    float s1 = 0.f, s2 = 0.f;
    for (int i = t; i < Bb * Nn; i += 256) {
        int b = i / Nn, n = i % Nn;
        float v = Y[(long)b * bsy + (long)o * Nn + n];
        s1 += v; s2 += v * v;
    }
    __shared__ float r1[256], r2[256];
    r1[t] = s1; r2[t] = s2;
    __syncthreads();
    for (int off = 128; off > 0; off >>= 1) {
        if (t < off) { r1[t] += r1[t + off]; r2[t] += r2[t + off]; }
        __syncthreads();
    }
    if (t == 0) {
        float m = r1[0] / (float)(Bb * Nn);
        float v = r2[0] / (float)(Bb * Nn) - m * m;
        mean[o] = m;
        rstd[o] = rsqrtf(v + 1e-5f);
    }
}

__global__ void k_bnapply(float* __restrict__ Y, long bsy, int O,
                          const float* __restrict__ mean, const float* __restrict__ rstd) {
    long total = (long)Bb * O * Nn;
    for (long i = (long)blockIdx.x * blockDim.x + threadIdx.x; i < total;
         i += (long)gridDim.x * blockDim.x) {
        int n = (int)(i % Nn);
        long bo = i / Nn;
        int o = (int)(bo % O);
        int b = (int)(bo / O);
        float* p = Y + (long)b * bsy + (long)o * Nn + n;
        float v = (*p - mean[o]) * rstd[o];
        *p = v >= 0.f ? v : 0.2f * v;
    }
}

__global__ void k_copy(const float* __restrict__ X, long bsx,
                       float* __restrict__ D, long bsd, int C) {
    long total = (long)Bb * C * Nn;
    for (long i = (long)blockIdx.x * blockDim.x + threadIdx.x; i < total;
         i += (long)gridDim.x * blockDim.x) {
        int n = (int)(i % Nn);
        long bc = i / Nn;
        int c = (int)(bc % C);
        int b = (int)(bc / C);
        D[(long)b * bsd + (long)c * Nn + n] = X[(long)b * bsx + (long)c * Nn + n];
    }
}

__global__ void k_pool(const float* __restrict__ X5, float* __restrict__ p) {
    int bc = blockIdx.x;
    int b = bc / 1024, c = bc % 1024;
    const float* xp = X5 + ((long)b * 1024 + c) * Nn;
    int t = threadIdx.x;
    float mx = -3e38f, sm = 0.f;
    for (int n = t; n < Nn; n += 256) { float v = xp[n]; mx = fmaxf(mx, v); sm += v; }
    __shared__ float smx[256], ssm[256];
    smx[t] = mx; ssm[t] = sm;
    __syncthreads();
    for (int off = 128; off > 0; off >>= 1) {
        if (t < off) { smx[t] = fmaxf(smx[t], smx[t + off]); ssm[t] += ssm[t + off]; }
        __syncthreads();
    }
    if (t == 0) {
        p[b * 2048 + c]        = smx[0];
        p[b * 2048 + 1024 + c] = ssm[0] / (float)Nn;
    }
}

__global__ void k_linear(const float* __restrict__ in, const float* __restrict__ W,
                         const float* __restrict__ bias, float* __restrict__ out,
                         int I, int O) {
    int w = (blockIdx.x * blockDim.x + threadIdx.x) >> 5;
    int lane = threadIdx.x & 31;
    if (w >= Bb * O) return;
    int b = w / O, o = w % O;
    const float* ip = in + (long)b * I;
    const float* wp = W + (long)o * I;
    float a = 0.f;
    for (int i = lane; i < I; i += 32) a += ip[i] * wp[i];
    for (int off = 16; off > 0; off >>= 1) a += __shfl_down_sync(0xffffffffu, a, off);
    if (lane == 0) out[w] = a + bias[o];
}

__global__ void k_bnf(float* __restrict__ Y, int O) {
    int o = blockIdx.x * blockDim.x + threadIdx.x;
    if (o >= O) return;
    float s1 = 0.f, s2 = 0.f;
    for (int b = 0; b < Bb; b++) { float v = Y[b * O + o]; s1 += v; s2 += v * v; }
    float m = s1 / (float)Bb;
    float v = s2 / (float)Bb - m * m;
    float r = rsqrtf(v + 1e-5f);
    for (int b = 0; b < Bb; b++) {
        float u = (Y[b * O + o] - m) * r;
        Y[b * O + o] = u >= 0.f ? u : 0.2f * u;
    }
}

// ---------------- host orchestration ----------------------------------------

static void gemm_h(const float* A, int lda, const float* X, long bsx,
                   int C, int O, float* Y, long bsy) {
    if (O % 128 == 0) {
        dim3 g(Nn / 128, O / 128, Bb);
        k_gemm<128, 8><<<g, 256>>>(A, lda, X, bsx, C, O, Y, bsy);
    } else {
        dim3 g(Nn / 128, (O + 63) / 64, Bb);
        k_gemm<64, 4><<<g, 256>>>(A, lda, X, bsx, C, O, Y, bsy);
    }
}

struct Scratch {
    float *pd, *sq, *att, *qk, *xt, *qkt, *wqk, *wcv, *h, *xc, *x5, *mean, *rstd, *p, *f1, *f2;
    int* idx;
};

static void conv_bn_h(const float* X, long bsx, int C, const float* W, int O,
                      float* Y, long bsy, float* mean, float* rstd) {
    gemm_h(W, C, X, bsx, C, O, Y, bsy);
    k_bnstats<<<O, 256>>>(Y, bsy, mean, rstd);
    long total = (long)Bb * O * Nn;
    k_bnapply<<<(int)((total + 255) / 256), 256>>>(Y, bsy, O, mean, rstd);
}

static void self_att_h(const float* X, long bsx, int C,
                       const float* wq, const float* wk, const float* wv, const float* wc,
                       float* H, long bsh, const Scratch& S) {
    k_sqnorm<<<(Bb * Nn + 255) / 256, 256>>>(X, bsx, C, S.sq);

    // symmetric dist (reads X directly, both operands)
    k_dist<<<dim3(136, 1, Bb), 256>>>(X, bsx, C, S.sq, S.pd);
    k_topk<<<Bb * Nn, 256>>>(S.pd, S.idx);

    // transpose X -> XT [B,N,C] (needed by attn2)
    dim3 tg(Nn / 32, (C + 31) / 32, Bb);
    k_transpose<<<tg, dim3(32, 8)>>>(X, bsx, C, S.xt);

    // Wqk = wk^T wq ; QK = Wqk @ X ; transpose -> QKT
    dim3 sg((C + 15) / 16, (C + 15) / 16);
    k_wqk<<<sg, dim3(16, 16)>>>(wk, wq, S.wqk, C);
    gemm_h(S.wqk, C, X, bsx, C, C, S.qk, (long)C * Nn);
    k_transpose<<<tg, dim3(32, 8)>>>(S.qk, (long)C * Nn, C, S.qkt);

    // gather + softmax + weighted diff -> M
    k_attn2<<<Bb * Nn / 32, 1024>>>(S.xt, S.qkt, C, S.idx, S.att, (long)C * Nn);

    // res = conv_bn(Wcv @ M)
    k_wcv<<<sg, dim3(16, 16)>>>(wc, wv, S.wcv, C);
    conv_bn_h(S.att, (long)C * Nn, C, S.wcv, C, H, bsh, S.mean, S.rstd);

    // concat raw x into channels [C, 2C)
    long total = (long)Bb * C * Nn;
    k_copy<<<(int)((total + 255) / 256), 256>>>(X, bsx, H + (long)C * Nn, bsh, C);
}

extern "C" void kernel_launch(void* const* d_in, const int* in_sizes, int n_in,
                              void* d_out, int out_size) {
    const float* x = (const float*)d_in[0];
    const float* sa_wq[4] = {(const float*)d_in[1],  (const float*)d_in[5],
                             (const float*)d_in[9],  (const float*)d_in[13]};
    const float* sa_wk[4] = {(const float*)d_in[2],  (const float*)d_in[6],
                             (const float*)d_in[10], (const float*)d_in[14]};
    const float* sa_wv[4] = {(const float*)d_in[3],  (const float*)d_in[7],
                             (const float*)d_in[11], (const float*)d_in[15]};
    const float* sa_wc[4] = {(const float*)d_in[4],  (const float*)d_in[8],
                             (const float*)d_in[12], (const float*)d_in[16]};
    const float* conv1_w = (const float*)d_in[17];
    const float* conv2_w = (const float*)d_in[18];
    const float* conv3_w = (const float*)d_in[19];
    const float* conv4_w = (const float*)d_in[20];
    const float* conv5_w = (const float*)d_in[21];
    const float* lin1_w = (const float*)d_in[22];
    const float* lin1_b = (const float*)d_in[23];
    const float* lin2_w = (const float*)d_in[24];
    const float* lin2_b = (const float*)d_in[25];
    const float* lin3_w = (const float*)d_in[26];
    const float* lin3_b = (const float*)d_in[27];

    Scratch S;
    cudaGetSymbolAddress((void**)&S.pd,   g_pd);
    cudaGetSymbolAddress((void**)&S.idx,  g_idx);
    cudaGetSymbolAddress((void**)&S.sq,   g_sq);
    cudaGetSymbolAddress((void**)&S.h,    g_h);
    cudaGetSymbolAddress((void**)&S.att,  g_att);
    cudaGetSymbolAddress((void**)&S.qk,   g_qk);
    cudaGetSymbolAddress((void**)&S.xt,   g_xt);
    cudaGetSymbolAddress((void**)&S.qkt,  g_qkt);
    cudaGetSymbolAddress((void**)&S.wqk,  g_wqk);
    cudaGetSymbolAddress((void**)&S.wcv,  g_wcv);
    cudaGetSymbolAddress((void**)&S.xc,   g_xc);
    cudaGetSymbolAddress((void**)&S.x5,   g_x5);
    cudaGetSymbolAddress((void**)&S.mean, g_mean);
    cudaGetSymbolAddress((void**)&S.rstd, g_rstd);
    cudaGetSymbolAddress((void**)&S.p,    g_p);
    cudaGetSymbolAddress((void**)&S.f1,   g_f1);
    cudaGetSymbolAddress((void**)&S.f2,   g_f2);

    const long bxc = (long)512 * Nn;

    self_att_h(x, (long)3 * Nn, 3, sa_wq[0], sa_wk[0], sa_wv[0], sa_wc[0],
               S.h, (long)6 * Nn, S);
    conv_bn_h(S.h, (long)6 * Nn, 6, conv1_w, 64, S.xc, bxc, S.mean, S.rstd);

    self_att_h(S.xc, bxc, 64, sa_wq[1], sa_wk[1], sa_wv[1], sa_wc[1],
               S.h, (long)128 * Nn, S);
    conv_bn_h(S.h, (long)128 * Nn, 128, conv2_w, 64, S.xc + (long)64 * Nn, bxc, S.mean, S.rstd);

    self_att_h(S.xc + (long)64 * Nn, bxc, 64, sa_wq[2], sa_wk[2], sa_wv[2], sa_wc[2],
               S.h, (long)128 * Nn, S);
    conv_bn_h(S.h, (long)128 * Nn, 128, conv3_w, 128, S.xc + (long)128 * Nn, bxc, S.mean, S.rstd);

    self_att_h(S.xc + (long)128 * Nn, bxc, 128, sa_wq[3], sa_wk[3], sa_wv[3], sa_wc[3],
               S.h, (long)256 * Nn, S);
    conv_bn_h(S.h, (long)256 * Nn, 256, conv4_w, 256, S.xc + (long)256 * Nn, bxc, S.mean, S.rstd);

    conv_bn_h(S.xc, bxc, 512, conv5_w, 1024, S.x5, (long)1024 * Nn, S.mean, S.rstd);

    k_pool<<<Bb * 1024, 256>>>(S.x5, S.p);

    k_linear<<<(Bb * 512 + 7) / 8, 256>>>(S.p, lin1_w, lin1_b, S.f1, 2048, 512);
    k_bnf<<<2, 256>>>(S.f1, 512);
    k_linear<<<(Bb * 256 + 7) / 8, 256>>>(S.f1, lin2_w, lin2_b, S.f2, 512, 256);
    k_bnf<<<1, 256>>>(S.f2, 256);
    k_linear<<<(Bb * 40 + 7) / 8, 256>>>(S.f2, lin3_w, lin3_b, (float*)d_out, 256, 40);
}